// round 3
// baseline (speedup 1.0000x reference)
#include <cuda_runtime.h>

#define TOTPTS 16384
#define NPTS   4096
#define KNN    16
#define PAD    132                     // H-buffer row stride (floats), 128 edges + pad
#define NGROUPS (TOTPTS / 8)           // 2048 groups of 8 points

#define MAIN_W_FLOATS   24576          // Ws2(64x64) + Ws3(128x64) + Ws4(192x64)
#define MAIN_H_FLOATS   (192 * PAD)    // H3|H2|H1 transposed, each 64 rows x 128 edges
#define MAIN_SMEM_BYTES ((MAIN_W_FLOATS + MAIN_H_FLOATS) * 4 + 128 * 4)

typedef unsigned long long u64;

// packed f32x2 helpers (FFMA2 path — PTX-only per sm_103a SASS docs)
#define FMA2(d, a, b, c) \
    asm("fma.rn.f32x2 %0, %1, %2, %3;" : "=l"(d) : "l"(a), "l"(b), "l"(c))
#define DUP2(d, s) \
    asm("mov.b64 %0, {%1, %1};" : "=l"(d) : "f"(s))
#define UNPK2(lo, hi, s) \
    asm("mov.b64 {%0, %1}, %2;" : "=f"(lo), "=f"(hi) : "l"(s))

// Scratch (allocation-free rule: device globals)
__device__ __align__(16) float g_L[TOTPTS * 256];   // [P | R1 | R2 | R3] per point
__device__ __align__(16) float g_Q[TOTPTS * 64];    // Q per point
__device__ int g_idx[TOTPTS * KNN];

// ---------------------------------------------------------------------------
// KNN v2: 8 sub-threads per query. Each sub scans 512 candidates (stride 8
// within shared tiles) keeping a private replace-max top-16; the 8 lists are
// merged per query. Global top-16 is a subset of the union of sub top-16s.
// Distance formula identical to R1 (qn + cn - 2*fmaf-dot).
// ---------------------------------------------------------------------------
__global__ __launch_bounds__(256) void knn_kernel(const float* __restrict__ pos) {
    __shared__ float4 sp[256];
    __shared__ float  sd[256 * KNN];
    __shared__ int    si[256 * KNN];

    int t   = threadIdx.x;
    int sub = t & 7;
    int ql  = t >> 3;                       // 0..31 query within block
    int qg  = blockIdx.x * 32 + ql;         // 0..16383
    int b   = qg >> 12;
    int q   = qg & 4095;
    const float* pb = pos + b * NPTS * 3;

    float qx = __ldg(pb + q * 3 + 0);
    float qy = __ldg(pb + q * 3 + 1);
    float qz = __ldg(pb + q * 3 + 2);
    float qn = qx * qx + qy * qy + qz * qz;

    float dv[KNN];
    int   iv[KNN];
#pragma unroll
    for (int r = 0; r < KNN; r++) { dv[r] = 3.0e38f; iv[r] = 0; }
    float dmax = 3.0e38f;
    int   amax = 0;

    for (int t0 = 0; t0 < NPTS; t0 += 256) {
        __syncthreads();
        {
            int j = t0 + t;
            float x = pb[j * 3 + 0], y = pb[j * 3 + 1], z = pb[j * 3 + 2];
            sp[t] = make_float4(x, y, z, x * x + y * y + z * z);
        }
        __syncthreads();
#pragma unroll 4
        for (int jj = 0; jj < 32; jj++) {
            int jl = sub + (jj << 3);
            float4 c = sp[jl];
            float dot = qx * c.x;
            dot = fmaf(qy, c.y, dot);
            dot = fmaf(qz, c.z, dot);
            float d2 = qn + c.w - 2.0f * dot;
            int jg = t0 + jl;
            if (d2 < dmax && jg != q) {
                dv[amax] = d2; iv[amax] = jg;
                dmax = dv[0]; amax = 0;
#pragma unroll
                for (int r = 1; r < KNN; r++)
                    if (dv[r] > dmax) { dmax = dv[r]; amax = r; }
            }
        }
    }

    // dump sub lists
#pragma unroll
    for (int r = 0; r < KNN; r++) {
        sd[t * KNN + r] = dv[r];
        si[t * KNN + r] = iv[r];
    }
    __syncthreads();

    // merge: one thread per query over 8*16 = 128 entries
    if (t < 32) {
        float md[KNN];
        int   mi[KNN];
#pragma unroll
        for (int r = 0; r < KNN; r++) { md[r] = 3.0e38f; mi[r] = 0; }
        float mmax = 3.0e38f;
        int   mam  = 0;
        int base = (t << 3) * KNN;          // entries for query ql = t
        for (int e = 0; e < 8 * KNN; e++) {
            float d2 = sd[base + e];
            if (d2 < mmax) {
                md[mam] = d2; mi[mam] = si[base + e];
                mmax = md[0]; mam = 0;
#pragma unroll
                for (int r = 1; r < KNN; r++)
                    if (md[r] > mmax) { mmax = md[r]; mam = r; }
            }
        }
        int obase = (blockIdx.x * 32 + t) * KNN;
#pragma unroll
        for (int r = 0; r < KNN; r++) g_idx[obase + r] = mi[r];
    }
}

// ---------------------------------------------------------------------------
// Per-point precompute: [P,Q,R1,R2,R3] = x @ combined 64x320 weight (+biases).
// ---------------------------------------------------------------------------
__global__ __launch_bounds__(256) void pre_kernel(
    const float* __restrict__ x,
    const float* __restrict__ Wf,  const float* __restrict__ bf,
    const float* __restrict__ Wm1, const float* __restrict__ bm1,
    const float* __restrict__ Wm2, const float* __restrict__ bm2,
    const float* __restrict__ Wl,  const float* __restrict__ bl) {

    __shared__ float sw[4096];        // current section weights 64x64
    __shared__ float sx[64 * 68];     // x tile transposed: sx[k][m], padded

    int t   = threadIdx.x;
    int pt0 = blockIdx.x * 64;

    for (int i = t; i < 4096; i += 256) {
        int r = i >> 6, c = i & 63;
        sx[c * 68 + r] = __ldg(x + (pt0 + r) * 64 + c);
    }

    int m0 = (t & 15) * 4;
    int n0 = (t >> 4) * 4;

    for (int sect = 0; sect < 5; sect++) {
        __syncthreads();
        for (int i = t; i < 4096; i += 256) {
            float v;
            if      (sect == 0) v = __ldg(Wf + i)        - __ldg(Wf + 8192 + i);
            else if (sect == 1) v = __ldg(Wf + 4096 + i) + __ldg(Wf + 8192 + i);
            else if (sect == 2) v = __ldg(Wm1 + 4096 + i);
            else if (sect == 3) v = __ldg(Wm2 + 8192 + i);
            else                v = __ldg(Wl + 12288 + i);
            sw[i] = v;
        }
        __syncthreads();

        float acc[4][4];
#pragma unroll
        for (int a = 0; a < 4; a++)
#pragma unroll
            for (int bq = 0; bq < 4; bq++) acc[a][bq] = 0.0f;

#pragma unroll 4
        for (int k = 0; k < 64; k++) {
            float4 av = *(const float4*)(sx + k * 68 + m0);
            float4 wv = *(const float4*)(sw + k * 64 + n0);
            float aa[4] = {av.x, av.y, av.z, av.w};
            float ww[4] = {wv.x, wv.y, wv.z, wv.w};
#pragma unroll
            for (int mi = 0; mi < 4; mi++)
#pragma unroll
                for (int ni = 0; ni < 4; ni++)
                    acc[mi][ni] = fmaf(aa[mi], ww[ni], acc[mi][ni]);
        }

        float4 bb = make_float4(0.f, 0.f, 0.f, 0.f);
        const float* bp = (sect == 0) ? bf : (sect == 2) ? bm1
                         : (sect == 3) ? bm2 : (sect == 4) ? bl : nullptr;
        if (bp) bb = __ldg((const float4*)(bp + n0));

#pragma unroll
        for (int mi = 0; mi < 4; mi++) {
            int pt = pt0 + m0 + mi;
            float4 o = make_float4(acc[mi][0] + bb.x, acc[mi][1] + bb.y,
                                   acc[mi][2] + bb.z, acc[mi][3] + bb.w);
            float* dst;
            if (sect == 1) dst = g_Q + pt * 64 + n0;
            else {
                int off = (sect == 0) ? 0 : (sect == 2) ? 64 : (sect == 3) ? 128 : 192;
                dst = g_L + pt * 256 + off + n0;
            }
            *(float4*)dst = o;
        }
    }
}

// ---------------------------------------------------------------------------
// Main edge-MLP + max kernel with packed f32x2 FMA (FFMA2).
// acc2[mp][ni] is an f32x2 pair covering edges (m0+2mp, m0+2mp+1), channel n0+ni.
// ---------------------------------------------------------------------------
template <int KD>
__device__ __forceinline__ void gemm_acc2(const float* __restrict__ a,
                                          const float* __restrict__ w,
                                          int m0, int n0, u64 acc[4][4]) {
#pragma unroll 4
    for (int k = 0; k < KD; k++) {
        ulonglong2 av0 = *(const ulonglong2*)(a + k * PAD + m0);
        ulonglong2 av1 = *(const ulonglong2*)(a + k * PAD + m0 + 4);
        float4 wv = *(const float4*)(w + k * 64 + n0);
        u64 ap[4] = {av0.x, av0.y, av1.x, av1.y};
        u64 wd[4];
        DUP2(wd[0], wv.x); DUP2(wd[1], wv.y);
        DUP2(wd[2], wv.z); DUP2(wd[3], wv.w);
#pragma unroll
        for (int mi = 0; mi < 4; mi++)
#pragma unroll
            for (int ni = 0; ni < 4; ni++)
                FMA2(acc[mi][ni], ap[mi], wd[ni], acc[mi][ni]);
    }
}

__device__ __forceinline__ void unpack_acc(const u64 acc[4][4], float f[8][4]) {
#pragma unroll
    for (int mp = 0; mp < 4; mp++)
#pragma unroll
        for (int ni = 0; ni < 4; ni++)
            UNPK2(f[2 * mp][ni], f[2 * mp + 1][ni], acc[mp][ni]);
}

__device__ __forceinline__ void store_relu_t(const float acc[8][4], float4 r,
                                             float* dstBase, int m0, int n0) {
    float rr[4] = {r.x, r.y, r.z, r.w};
#pragma unroll
    for (int ni = 0; ni < 4; ni++) {
        float4 lo = make_float4(fmaxf(acc[0][ni] + rr[ni], 0.f),
                                fmaxf(acc[1][ni] + rr[ni], 0.f),
                                fmaxf(acc[2][ni] + rr[ni], 0.f),
                                fmaxf(acc[3][ni] + rr[ni], 0.f));
        float4 hi = make_float4(fmaxf(acc[4][ni] + rr[ni], 0.f),
                                fmaxf(acc[5][ni] + rr[ni], 0.f),
                                fmaxf(acc[6][ni] + rr[ni], 0.f),
                                fmaxf(acc[7][ni] + rr[ni], 0.f));
        *(float4*)(dstBase + (n0 + ni) * PAD + m0)     = lo;
        *(float4*)(dstBase + (n0 + ni) * PAD + m0 + 4) = hi;
    }
}

__global__ __launch_bounds__(256, 1) void edge_mlp_kernel(
    const float* __restrict__ x,
    const float* __restrict__ Wm1,  // uses first 64 rows (4096 floats)
    const float* __restrict__ Wm2,  // uses first 128 rows (8192 floats)
    const float* __restrict__ Wl,   // uses first 192 rows (12288 floats)
    float* __restrict__ out) {

    extern __shared__ float smem[];
    float* s_w  = smem;                       // 24576 floats
    float* s_h  = smem + MAIN_W_FLOATS;       // 192*PAD floats
    int*   s_id = (int*)(smem + MAIN_W_FLOATS + MAIN_H_FLOATS);  // 128 ints

    int t = threadIdx.x;

    for (int i = t; i < 1024; i += 256)
        ((float4*)s_w)[i] = __ldg((const float4*)Wm1 + i);
    for (int i = t; i < 2048; i += 256)
        ((float4*)(s_w + 4096))[i] = __ldg((const float4*)Wm2 + i);
    for (int i = t; i < 3072; i += 256)
        ((float4*)(s_w + 12288))[i] = __ldg((const float4*)Wl + i);
    __syncthreads();

    const int m0 = (t & 15) * 8;       // 8 edges per thread
    const int n0 = (t >> 4) * 4;       // 4 output channels per thread
    const int p_local = (t & 15) >> 1; // point owning this thread's edges

    for (int g = blockIdx.x; g < NGROUPS; g += gridDim.x) {
        int ptg0 = g * 8;
        int b    = ptg0 >> 12;

        if (t < 128) s_id[t] = g_idx[ptg0 * KNN + t];
        __syncthreads();

        // ---- Gather: H1[c][m] = relu(P[pt][c] + Q[nbr][c]) ----
        for (int i = t; i < 2048; i += 256) {
            int m  = i & 127;
            int cq = i >> 7;
            int j  = s_id[m];
            int pt = ptg0 + (m >> 4);
            float4 qv = __ldg((const float4*)(g_Q + ((b << 12) + j) * 64 + cq * 4));
            float4 pv = __ldg((const float4*)(g_L + pt * 256 + cq * 4));
            float* hb = s_h + (128 + cq * 4) * PAD + m;
            hb[0 * PAD] = fmaxf(pv.x + qv.x, 0.f);
            hb[1 * PAD] = fmaxf(pv.y + qv.y, 0.f);
            hb[2 * PAD] = fmaxf(pv.z + qv.z, 0.f);
            hb[3 * PAD] = fmaxf(pv.w + qv.w, 0.f);
        }
        __syncthreads();

        int ptg = ptg0 + p_local;

        // ---- Step 2: H2 = relu(H1 @ Ws2 + R1) ----
        {
            u64 acc[4][4] = {};
            gemm_acc2<64>(s_h + 128 * PAD, s_w, m0, n0, acc);
            float f[8][4];
            unpack_acc(acc, f);
            float4 r = __ldg((const float4*)(g_L + ptg * 256 + 64 + n0));
            store_relu_t(f, r, s_h + 64 * PAD, m0, n0);
        }
        __syncthreads();

        // ---- Step 3: H3 = relu([H2|H1] @ Ws3 + R2) ----
        {
            u64 acc[4][4] = {};
            gemm_acc2<128>(s_h + 64 * PAD, s_w + 4096, m0, n0, acc);
            float f[8][4];
            unpack_acc(acc, f);
            float4 r = __ldg((const float4*)(g_L + ptg * 256 + 128 + n0));
            store_relu_t(f, r, s_h, m0, n0);
        }
        __syncthreads();

        // ---- Step 4: H4 = [H3|H2|H1] @ Ws4 + R3 (no relu), fused max over K ----
        {
            u64 acc[4][4] = {};
            gemm_acc2<192>(s_h, s_w + 12288, m0, n0, acc);
            float f[8][4];
            unpack_acc(acc, f);
            float4 r3 = __ldg((const float4*)(g_L + ptg * 256 + 192 + n0));
            float vmax[4];
#pragma unroll
            for (int ni = 0; ni < 4; ni++) {
                float v = f[0][ni];
#pragma unroll
                for (int mi = 1; mi < 8; mi++) v = fmaxf(v, f[mi][ni]);
                vmax[ni] = v;
            }
            vmax[0] += r3.x; vmax[1] += r3.y; vmax[2] += r3.z; vmax[3] += r3.w;
#pragma unroll
            for (int ni = 0; ni < 4; ni++)
                vmax[ni] = fmaxf(vmax[ni], __shfl_xor_sync(0xffffffffu, vmax[ni], 1));
            if ((t & 1) == 0)
                *(float4*)(out + ptg * 320 + n0) =
                    make_float4(vmax[0], vmax[1], vmax[2], vmax[3]);
        }

        // ---- Max over K for H3/H2/H1 directly from smem ----
        for (int i = t; i < 1536; i += 256) {
            int p   = i / 192;
            int row = i - p * 192;
            const float* hp = s_h + row * PAD + p * 16;
            float v = hp[0];
#pragma unroll
            for (int k2 = 1; k2 < 16; k2++) v = fmaxf(v, hp[k2]);
            out[(ptg0 + p) * 320 + 64 + row] = v;
        }

        // ---- x passthrough ----
        for (int i = t; i < 512; i += 256) {
            int p = i >> 6, c = i & 63;
            out[(ptg0 + p) * 320 + 256 + c] = __ldg(x + (ptg0 + p) * 64 + c);
        }
        __syncthreads();
    }
}

// ---------------------------------------------------------------------------
extern "C" void kernel_launch(void* const* d_in, const int* in_sizes, int n_in,
                              void* d_out, int out_size) {
    const float* x   = (const float*)d_in[0];
    const float* pos = (const float*)d_in[1];
    const float* Wf  = (const float*)d_in[2];
    const float* bf  = (const float*)d_in[3];
    const float* Wm1 = (const float*)d_in[4];
    const float* bm1 = (const float*)d_in[5];
    const float* Wm2 = (const float*)d_in[6];
    const float* bm2 = (const float*)d_in[7];
    const float* Wl  = (const float*)d_in[8];
    const float* bl  = (const float*)d_in[9];
    float* out = (float*)d_out;

    cudaFuncSetAttribute(edge_mlp_kernel,
                         cudaFuncAttributeMaxDynamicSharedMemorySize,
                         MAIN_SMEM_BYTES);

    knn_kernel<<<512, 256>>>(pos);
    pre_kernel<<<256, 256>>>(x, Wf, bf, Wm1, bm1, Wm2, bm2, Wl, bl);
    edge_mlp_kernel<<<148, 256, MAIN_SMEM_BYTES>>>(x, Wm1, Wm2, Wl, out);
}

// round 4
// speedup vs baseline: 1.3138x; 1.3138x over previous
#include <cuda_runtime.h>

#define TOTPTS 16384
#define NPTS   4096
#define KNN    16
#define PAD    132                     // H-buffer row stride (floats), 128 edges + pad
#define NGROUPS (TOTPTS / 8)           // 2048 groups of 8 points

#define MAIN_W_FLOATS   24576          // Ws2(64x64) + Ws3(128x64) + Ws4(192x64)
#define MAIN_H_FLOATS   (192 * PAD)    // H3|H2|H1 transposed, each 64 rows x 128 edges
#define MAIN_SMEM_BYTES ((MAIN_W_FLOATS + MAIN_H_FLOATS) * 4 + 128 * 4)

// knn filter/refine config
#define QPB  32                        // queries per block
#define TILE 256                       // candidates per tile
#define BUFN 256                       // buffer entries per query (== TILE, overflow-proof)
#define KNN_SMEM_BYTES (TILE * 16 + 2 * QPB * BUFN * 4 + QPB * 4 + QPB * 4)

// Scratch (allocation-free rule: device globals)
__device__ __align__(16) float g_L[TOTPTS * 256];   // [P | R1 | R2 | R3] per point
__device__ __align__(16) float g_Q[TOTPTS * 64];    // Q per point
__device__ int g_idx[TOTPTS * KNN];

// ---------------------------------------------------------------------------
// KNN v4: filter/refine with shared exact threshold.
// 256 threads = 32 queries x 8 subs. Hot loop is warp-coherent: compare d2
// against tau (the query's exact 16th-smallest so far); passing candidates
// (rare) are pushed to a per-query smem buffer with a tiny predicated path.
// After each 256-candidate tile, thread t<32 drains query t's buffer through
// a register-resident replace-max top-16 and tightens tau. Exact result:
// tau >= true running 16th at all times, so no true neighbor is ever pruned.
// Distance formula identical to R1/R2 (qn + cn - 2*fmaf-dot).
// ---------------------------------------------------------------------------
__global__ __launch_bounds__(256) void knn_kernel(const float* __restrict__ pos) {
    extern __shared__ char kshm[];
    float4* sp   = (float4*)kshm;                                  // 4 KB
    float*  bufD = (float*)(kshm + TILE * 16);                     // 32 KB
    int*    bufI = (int*)(kshm + TILE * 16 + QPB * BUFN * 4);      // 32 KB
    int*    scnt = (int*)(kshm + TILE * 16 + 2 * QPB * BUFN * 4);  // 128 B
    float*  stau = (float*)(kshm + TILE * 16 + 2 * QPB * BUFN * 4 + QPB * 4);

    int t   = threadIdx.x;
    int ql  = t >> 3;                      // 0..31 query within block
    int sub = t & 7;
    int qg  = blockIdx.x * QPB + ql;       // global point id 0..16383
    int b   = qg >> 12;
    int q   = qg & 4095;                   // index within batch
    const float* pb = pos + b * NPTS * 3;

    if (t < QPB) { scnt[t] = 0; stau[t] = 3.0e38f; }

    float qx = __ldg(pb + q * 3 + 0);
    float qy = __ldg(pb + q * 3 + 1);
    float qz = __ldg(pb + q * 3 + 2);
    float qn = qx * qx + qy * qy + qz * qz;

    // refine state (used only by t < QPB)
    float dv[KNN];
    int   iv[KNN];
#pragma unroll
    for (int r = 0; r < KNN; r++) { dv[r] = 3.0e38f; iv[r] = 0; }
    float dmax = 3.0e38f;
    int   amax = 0;

    for (int t0 = 0; t0 < NPTS; t0 += TILE) {
        __syncthreads();   // previous refine done: buffer free, stau current, sp reusable
        {
            int j = t0 + t;
            float x = pb[j * 3 + 0], y = pb[j * 3 + 1], z = pb[j * 3 + 2];
            sp[t] = make_float4(x, y, z, x * x + y * y + z * z);
        }
        __syncthreads();

        float tau = stau[ql];
        float* bD = bufD + ql * BUFN;
        int*   bI = bufI + ql * BUFN;

#pragma unroll 8
        for (int jj = 0; jj < TILE / 8; jj++) {
            int jl = sub + (jj << 3);
            float4 c = sp[jl];
            float dot = qx * c.x;
            dot = fmaf(qy, c.y, dot);
            dot = fmaf(qz, c.z, dot);
            float d2 = fmaf(dot, -2.0f, qn + c.w);
            int jg = t0 + jl;
            if (d2 < tau && jg != q) {
                int slot = atomicAdd(&scnt[ql], 1);
                bD[slot] = d2;
                bI[slot] = jg;
            }
        }
        __syncthreads();

        // refine: one thread per query drains its buffer (exact top-16)
        if (t < QPB) {
            int n = scnt[t];
            const float* rD = bufD + t * BUFN;
            const int*   rI = bufI + t * BUFN;
            for (int e = 0; e < n; e++) {
                float d2 = rD[e];
                if (d2 < dmax) {
                    dv[amax] = d2; iv[amax] = rI[e];
                    dmax = dv[0]; amax = 0;
#pragma unroll
                    for (int r = 1; r < KNN; r++)
                        if (dv[r] > dmax) { dmax = dv[r]; amax = r; }
                }
            }
            scnt[t] = 0;
            stau[t] = dmax;
        }
    }

    if (t < QPB) {
        int obase = (blockIdx.x * QPB + t) * KNN;
#pragma unroll
        for (int r = 0; r < KNN; r++) g_idx[obase + r] = iv[r];
    }
}

// ---------------------------------------------------------------------------
// Per-point precompute: [P,Q,R1,R2,R3] = x @ combined 64x320 weight (+biases).
// ---------------------------------------------------------------------------
__global__ __launch_bounds__(256) void pre_kernel(
    const float* __restrict__ x,
    const float* __restrict__ Wf,  const float* __restrict__ bf,
    const float* __restrict__ Wm1, const float* __restrict__ bm1,
    const float* __restrict__ Wm2, const float* __restrict__ bm2,
    const float* __restrict__ Wl,  const float* __restrict__ bl) {

    __shared__ float sw[4096];        // current section weights 64x64
    __shared__ float sx[64 * 68];     // x tile transposed: sx[k][m], padded

    int t   = threadIdx.x;
    int pt0 = blockIdx.x * 64;

    for (int i = t; i < 4096; i += 256) {
        int r = i >> 6, c = i & 63;
        sx[c * 68 + r] = __ldg(x + (pt0 + r) * 64 + c);
    }

    int m0 = (t & 15) * 4;
    int n0 = (t >> 4) * 4;

    for (int sect = 0; sect < 5; sect++) {
        __syncthreads();
        for (int i = t; i < 4096; i += 256) {
            float v;
            if      (sect == 0) v = __ldg(Wf + i)        - __ldg(Wf + 8192 + i);
            else if (sect == 1) v = __ldg(Wf + 4096 + i) + __ldg(Wf + 8192 + i);
            else if (sect == 2) v = __ldg(Wm1 + 4096 + i);
            else if (sect == 3) v = __ldg(Wm2 + 8192 + i);
            else                v = __ldg(Wl + 12288 + i);
            sw[i] = v;
        }
        __syncthreads();

        float acc[4][4];
#pragma unroll
        for (int a = 0; a < 4; a++)
#pragma unroll
            for (int bq = 0; bq < 4; bq++) acc[a][bq] = 0.0f;

#pragma unroll 4
        for (int k = 0; k < 64; k++) {
            float4 av = *(const float4*)(sx + k * 68 + m0);
            float4 wv = *(const float4*)(sw + k * 64 + n0);
            float aa[4] = {av.x, av.y, av.z, av.w};
            float ww[4] = {wv.x, wv.y, wv.z, wv.w};
#pragma unroll
            for (int mi = 0; mi < 4; mi++)
#pragma unroll
                for (int ni = 0; ni < 4; ni++)
                    acc[mi][ni] = fmaf(aa[mi], ww[ni], acc[mi][ni]);
        }

        float4 bb = make_float4(0.f, 0.f, 0.f, 0.f);
        const float* bp = (sect == 0) ? bf : (sect == 2) ? bm1
                         : (sect == 3) ? bm2 : (sect == 4) ? bl : nullptr;
        if (bp) bb = __ldg((const float4*)(bp + n0));

#pragma unroll
        for (int mi = 0; mi < 4; mi++) {
            int pt = pt0 + m0 + mi;
            float4 o = make_float4(acc[mi][0] + bb.x, acc[mi][1] + bb.y,
                                   acc[mi][2] + bb.z, acc[mi][3] + bb.w);
            float* dst;
            if (sect == 1) dst = g_Q + pt * 64 + n0;
            else {
                int off = (sect == 0) ? 0 : (sect == 2) ? 64 : (sect == 3) ? 128 : 192;
                dst = g_L + pt * 256 + off + n0;
            }
            *(float4*)dst = o;
        }
    }
}

// ---------------------------------------------------------------------------
// Main edge-MLP + max kernel (scalar fp32 — proven R2 version).
// ---------------------------------------------------------------------------
template <int KD>
__device__ __forceinline__ void gemm_acc(const float* __restrict__ a,
                                         const float* __restrict__ w,
                                         int m0, int n0, float acc[8][4]) {
#pragma unroll 4
    for (int k = 0; k < KD; k++) {
        float4 a0 = *(const float4*)(a + k * PAD + m0);
        float4 a1 = *(const float4*)(a + k * PAD + m0 + 4);
        float4 wv = *(const float4*)(w + k * 64 + n0);
        float av[8] = {a0.x, a0.y, a0.z, a0.w, a1.x, a1.y, a1.z, a1.w};
        float ww[4] = {wv.x, wv.y, wv.z, wv.w};
#pragma unroll
        for (int mi = 0; mi < 8; mi++)
#pragma unroll
            for (int ni = 0; ni < 4; ni++)
                acc[mi][ni] = fmaf(av[mi], ww[ni], acc[mi][ni]);
    }
}

__device__ __forceinline__ void store_relu_t(const float acc[8][4], float4 r,
                                             float* dstBase, int m0, int n0) {
    float rr[4] = {r.x, r.y, r.z, r.w};
#pragma unroll
    for (int ni = 0; ni < 4; ni++) {
        float4 lo = make_float4(fmaxf(acc[0][ni] + rr[ni], 0.f),
                                fmaxf(acc[1][ni] + rr[ni], 0.f),
                                fmaxf(acc[2][ni] + rr[ni], 0.f),
                                fmaxf(acc[3][ni] + rr[ni], 0.f));
        float4 hi = make_float4(fmaxf(acc[4][ni] + rr[ni], 0.f),
                                fmaxf(acc[5][ni] + rr[ni], 0.f),
                                fmaxf(acc[6][ni] + rr[ni], 0.f),
                                fmaxf(acc[7][ni] + rr[ni], 0.f));
        *(float4*)(dstBase + (n0 + ni) * PAD + m0)     = lo;
        *(float4*)(dstBase + (n0 + ni) * PAD + m0 + 4) = hi;
    }
}

__global__ __launch_bounds__(256, 1) void edge_mlp_kernel(
    const float* __restrict__ x,
    const float* __restrict__ Wm1,  // uses first 64 rows (4096 floats)
    const float* __restrict__ Wm2,  // uses first 128 rows (8192 floats)
    const float* __restrict__ Wl,   // uses first 192 rows (12288 floats)
    float* __restrict__ out) {

    extern __shared__ float smem[];
    float* s_w  = smem;                       // 24576 floats
    float* s_h  = smem + MAIN_W_FLOATS;       // 192*PAD floats
    int*   s_id = (int*)(smem + MAIN_W_FLOATS + MAIN_H_FLOATS);  // 128 ints

    int t = threadIdx.x;

    for (int i = t; i < 1024; i += 256)
        ((float4*)s_w)[i] = __ldg((const float4*)Wm1 + i);
    for (int i = t; i < 2048; i += 256)
        ((float4*)(s_w + 4096))[i] = __ldg((const float4*)Wm2 + i);
    for (int i = t; i < 3072; i += 256)
        ((float4*)(s_w + 12288))[i] = __ldg((const float4*)Wl + i);
    __syncthreads();

    const int m0 = (t & 15) * 8;       // 8 edges per thread
    const int n0 = (t >> 4) * 4;       // 4 output channels per thread
    const int p_local = (t & 15) >> 1; // point owning this thread's edges

    for (int g = blockIdx.x; g < NGROUPS; g += gridDim.x) {
        int ptg0 = g * 8;
        int b    = ptg0 >> 12;

        if (t < 128) s_id[t] = g_idx[ptg0 * KNN + t];
        __syncthreads();

        // ---- Gather: H1[c][m] = relu(P[pt][c] + Q[nbr][c]) ----
        for (int i = t; i < 2048; i += 256) {
            int m  = i & 127;
            int cq = i >> 7;
            int j  = s_id[m];
            int pt = ptg0 + (m >> 4);
            float4 qv = __ldg((const float4*)(g_Q + ((b << 12) + j) * 64 + cq * 4));
            float4 pv = __ldg((const float4*)(g_L + pt * 256 + cq * 4));
            float* hb = s_h + (128 + cq * 4) * PAD + m;
            hb[0 * PAD] = fmaxf(pv.x + qv.x, 0.f);
            hb[1 * PAD] = fmaxf(pv.y + qv.y, 0.f);
            hb[2 * PAD] = fmaxf(pv.z + qv.z, 0.f);
            hb[3 * PAD] = fmaxf(pv.w + qv.w, 0.f);
        }
        __syncthreads();

        int ptg = ptg0 + p_local;

        // ---- Step 2: H2 = relu(H1 @ Ws2 + R1) ----
        {
            float acc[8][4];
#pragma unroll
            for (int a = 0; a < 8; a++)
#pragma unroll
                for (int bq = 0; bq < 4; bq++) acc[a][bq] = 0.f;
            gemm_acc<64>(s_h + 128 * PAD, s_w, m0, n0, acc);
            float4 r = __ldg((const float4*)(g_L + ptg * 256 + 64 + n0));
            store_relu_t(acc, r, s_h + 64 * PAD, m0, n0);
        }
        __syncthreads();

        // ---- Step 3: H3 = relu([H2|H1] @ Ws3 + R2) ----
        {
            float acc[8][4];
#pragma unroll
            for (int a = 0; a < 8; a++)
#pragma unroll
                for (int bq = 0; bq < 4; bq++) acc[a][bq] = 0.f;
            gemm_acc<128>(s_h + 64 * PAD, s_w + 4096, m0, n0, acc);
            float4 r = __ldg((const float4*)(g_L + ptg * 256 + 128 + n0));
            store_relu_t(acc, r, s_h, m0, n0);
        }
        __syncthreads();

        // ---- Step 4: H4 = [H3|H2|H1] @ Ws4 + R3 (no relu), fused max over K ----
        {
            float acc[8][4];
#pragma unroll
            for (int a = 0; a < 8; a++)
#pragma unroll
                for (int bq = 0; bq < 4; bq++) acc[a][bq] = 0.f;
            gemm_acc<192>(s_h, s_w + 12288, m0, n0, acc);
            float4 r3 = __ldg((const float4*)(g_L + ptg * 256 + 192 + n0));
            float vmax[4];
#pragma unroll
            for (int ni = 0; ni < 4; ni++) {
                float v = acc[0][ni];
#pragma unroll
                for (int mi = 1; mi < 8; mi++) v = fmaxf(v, acc[mi][ni]);
                vmax[ni] = v;
            }
            vmax[0] += r3.x; vmax[1] += r3.y; vmax[2] += r3.z; vmax[3] += r3.w;
#pragma unroll
            for (int ni = 0; ni < 4; ni++)
                vmax[ni] = fmaxf(vmax[ni], __shfl_xor_sync(0xffffffffu, vmax[ni], 1));
            if ((t & 1) == 0)
                *(float4*)(out + ptg * 320 + n0) =
                    make_float4(vmax[0], vmax[1], vmax[2], vmax[3]);
        }

        // ---- Max over K for H3/H2/H1 directly from smem ----
        for (int i = t; i < 1536; i += 256) {
            int p   = i / 192;
            int row = i - p * 192;
            const float* hp = s_h + row * PAD + p * 16;
            float v = hp[0];
#pragma unroll
            for (int k2 = 1; k2 < 16; k2++) v = fmaxf(v, hp[k2]);
            out[(ptg0 + p) * 320 + 64 + row] = v;
        }

        // ---- x passthrough ----
        for (int i = t; i < 512; i += 256) {
            int p = i >> 6, c = i & 63;
            out[(ptg0 + p) * 320 + 256 + c] = __ldg(x + (ptg0 + p) * 64 + c);
        }
        __syncthreads();
    }
}

// ---------------------------------------------------------------------------
extern "C" void kernel_launch(void* const* d_in, const int* in_sizes, int n_in,
                              void* d_out, int out_size) {
    const float* x   = (const float*)d_in[0];
    const float* pos = (const float*)d_in[1];
    const float* Wf  = (const float*)d_in[2];
    const float* bf  = (const float*)d_in[3];
    const float* Wm1 = (const float*)d_in[4];
    const float* bm1 = (const float*)d_in[5];
    const float* Wm2 = (const float*)d_in[6];
    const float* bm2 = (const float*)d_in[7];
    const float* Wl  = (const float*)d_in[8];
    const float* bl  = (const float*)d_in[9];
    float* out = (float*)d_out;

    cudaFuncSetAttribute(knn_kernel,
                         cudaFuncAttributeMaxDynamicSharedMemorySize,
                         KNN_SMEM_BYTES);
    cudaFuncSetAttribute(edge_mlp_kernel,
                         cudaFuncAttributeMaxDynamicSharedMemorySize,
                         MAIN_SMEM_BYTES);

    knn_kernel<<<TOTPTS / QPB, 256, KNN_SMEM_BYTES>>>(pos);
    pre_kernel<<<256, 256>>>(x, Wf, bf, Wm1, bm1, Wm2, bm2, Wl, bl);
    edge_mlp_kernel<<<148, 256, MAIN_SMEM_BYTES>>>(x, Wm1, Wm2, Wl, out);
}

// round 6
// speedup vs baseline: 1.5234x; 1.1595x over previous
#include <cuda_runtime.h>

#define TOTPTS 16384
#define NPTS   4096
#define KNN    16
#define PAD    132                     // H-buffer row stride (floats), 128 edges + pad
#define NGROUPS (TOTPTS / 8)           // 2048 groups of 8 points

#define MAIN_W_FLOATS   24576          // Ws2(64x64) + Ws3(128x64) + Ws4(192x64)
#define MAIN_H_FLOATS   (192 * PAD)    // H3|H2|H1 transposed, each 64 rows x 128 edges
#define MAIN_SMEM_BYTES ((MAIN_W_FLOATS + MAIN_H_FLOATS) * 4 + 128 * 4)

// knn config
#define QPB  32                        // queries per block
#define TILE 256                       // candidates per tile
// smem: sp(4KB) + bufI(32KB) + seedD(2KB) + seedI(2KB) + scnt(128B) + stau(128B)
#define KNN_SMEM_BYTES (TILE * 16 + QPB * TILE * 4 + QPB * KNN * 4 * 2 + QPB * 8)

// Scratch (allocation-free rule: device globals)
__device__ __align__(16) float g_L[TOTPTS * 256];   // [P | R1 | R2 | R3] per point
__device__ __align__(16) float g_Q[TOTPTS * 64];    // Q per point
__device__ int g_idx[TOTPTS * KNN];

// ---------------------------------------------------------------------------
// KNN v5: two-phase with provable pre-threshold.
// Phase A: each (query,sub) keeps a register top-2 over its 512 candidates
//   (cheap, mostly-coherent). Union of 8 subs' top-2 = 16 distinct elements;
//   tau0 = max(union) >= true 16th-smallest (16-subset max bounds the 16th
//   order statistic). Refine list is seeded with these 16 pairs.
// Phase B: tiled filter with tau (starts at tau0, tightens per tile). Passes
//   are rare from tile 0. Buffer stores LOCAL tile index only; refine thread
//   recomputes d2 from the still-resident sp tile (bit-identical formula) and
//   dedupes by global index against the current list (seeds are the only
//   possible duplicates). Exact top-16, same selection as R1-R4.
// ---------------------------------------------------------------------------
__global__ __launch_bounds__(256) void knn_kernel(const float* __restrict__ pos) {
    extern __shared__ char kshm[];
    float4* sp    = (float4*)kshm;                                     // 4 KB
    int*    bufI  = (int*)(kshm + TILE * 16);                          // 32 KB
    float*  seedD = (float*)(kshm + TILE * 16 + QPB * TILE * 4);       // 2 KB
    int*    seedI = (int*)(kshm + TILE * 16 + QPB * TILE * 4 + QPB * KNN * 4);
    int*    scnt  = (int*)(kshm + TILE * 16 + QPB * TILE * 4 + QPB * KNN * 8);
    float*  stau  = (float*)(kshm + TILE * 16 + QPB * TILE * 4 + QPB * KNN * 8 + QPB * 4);

    int t   = threadIdx.x;
    int ql  = t >> 3;                      // 0..31 query within block
    int sub = t & 7;
    int qg  = blockIdx.x * QPB + ql;       // global point id
    int b   = qg >> 12;
    int q   = qg & 4095;
    const float* pb = pos + b * NPTS * 3;

    if (t < QPB) scnt[t] = 0;

    float qx = __ldg(pb + q * 3 + 0);
    float qy = __ldg(pb + q * 3 + 1);
    float qz = __ldg(pb + q * 3 + 2);
    float qn = qx * qx + qy * qy + qz * qz;

    // refine-thread query coords (thread t < QPB owns query t of this block)
    float rqx = 0.f, rqy = 0.f, rqz = 0.f, rqn = 0.f;
    if (t < QPB) {
        int rq = (blockIdx.x * QPB + t) & 4095;
        rqx = __ldg(pb + rq * 3 + 0);
        rqy = __ldg(pb + rq * 3 + 1);
        rqz = __ldg(pb + rq * 3 + 2);
        rqn = rqx * rqx + rqy * rqy + rqz * rqz;
    }

    // ---- Phase A: per-(query,sub) top-2 ----
    float s0 = 3.0e38f, s1 = 3.0e38f;
    int   i0 = 0,       i1 = 0;

    for (int t0 = 0; t0 < NPTS; t0 += TILE) {
        __syncthreads();
        {
            int j = t0 + t;
            float x = pb[j * 3 + 0], y = pb[j * 3 + 1], z = pb[j * 3 + 2];
            sp[t] = make_float4(x, y, z, x * x + y * y + z * z);
        }
        __syncthreads();
#pragma unroll 8
        for (int jj = 0; jj < TILE / 8; jj++) {
            int jl = sub + (jj << 3);
            float4 c = sp[jl];
            float dot = qx * c.x;
            dot = fmaf(qy, c.y, dot);
            dot = fmaf(qz, c.z, dot);
            float d2 = fmaf(dot, -2.0f, qn + c.w);
            int jg = t0 + jl;
            if (d2 < s1 && jg != q) {
                if (d2 < s0) { s1 = s0; i1 = i0; s0 = d2; i0 = jg; }
                else         { s1 = d2; i1 = jg; }
            }
        }
    }
    seedD[ql * KNN + sub * 2 + 0] = s0;
    seedI[ql * KNN + sub * 2 + 0] = i0;
    seedD[ql * KNN + sub * 2 + 1] = s1;
    seedI[ql * KNN + sub * 2 + 1] = i1;
    __syncthreads();

    // ---- Seed refine state from the 16 collected pairs; tau0 = their max ----
    float dv[KNN];
    int   iv[KNN];
    float dmax = 0.f;
    int   amax = 0;
    if (t < QPB) {
#pragma unroll
        for (int r = 0; r < KNN; r++) {
            dv[r] = seedD[t * KNN + r];
            iv[r] = seedI[t * KNN + r];
        }
        dmax = dv[0]; amax = 0;
#pragma unroll
        for (int r = 1; r < KNN; r++)
            if (dv[r] > dmax) { dmax = dv[r]; amax = r; }
        stau[t] = dmax;
    }

    // ---- Phase B: filter with tight tau + tiny per-tile refine ----
    for (int t0 = 0; t0 < NPTS; t0 += TILE) {
        __syncthreads();   // stau/scnt settled; sp reusable
        {
            int j = t0 + t;
            float x = pb[j * 3 + 0], y = pb[j * 3 + 1], z = pb[j * 3 + 2];
            sp[t] = make_float4(x, y, z, x * x + y * y + z * z);
        }
        __syncthreads();

        float tau = stau[ql];
        int*  bI  = bufI + ql * TILE;

#pragma unroll 8
        for (int jj = 0; jj < TILE / 8; jj++) {
            int jl = sub + (jj << 3);
            float4 c = sp[jl];
            float dot = qx * c.x;
            dot = fmaf(qy, c.y, dot);
            dot = fmaf(qz, c.z, dot);
            float d2 = fmaf(dot, -2.0f, qn + c.w);
            int jg = t0 + jl;
            if (d2 < tau && jg != q) {
                int slot = atomicAdd(&scnt[ql], 1);
                bI[slot] = jl;
            }
        }
        __syncthreads();

        if (t < QPB) {
            int n = scnt[t];
            const int* rI = bufI + t * TILE;
            for (int e = 0; e < n; e++) {
                int jl = rI[e];
                float4 c = sp[jl];
                float dot = rqx * c.x;
                dot = fmaf(rqy, c.y, dot);
                dot = fmaf(rqz, c.z, dot);
                float d2 = fmaf(dot, -2.0f, rqn + c.w);
                if (d2 < dmax) {
                    int jg = t0 + jl;
                    bool dup = false;
#pragma unroll
                    for (int r = 0; r < KNN; r++) dup = dup || (iv[r] == jg);
                    if (!dup) {
                        dv[amax] = d2; iv[amax] = jg;
                        dmax = dv[0]; amax = 0;
#pragma unroll
                        for (int r = 1; r < KNN; r++)
                            if (dv[r] > dmax) { dmax = dv[r]; amax = r; }
                    }
                }
            }
            scnt[t] = 0;
            stau[t] = dmax;
        }
    }

    if (t < QPB) {
        int obase = (blockIdx.x * QPB + t) * KNN;
#pragma unroll
        for (int r = 0; r < KNN; r++) g_idx[obase + r] = iv[r];
    }
}

// ---------------------------------------------------------------------------
// Per-point precompute: [P,Q,R1,R2,R3] = x @ combined 64x320 weight (+biases).
// ---------------------------------------------------------------------------
__global__ __launch_bounds__(256) void pre_kernel(
    const float* __restrict__ x,
    const float* __restrict__ Wf,  const float* __restrict__ bf,
    const float* __restrict__ Wm1, const float* __restrict__ bm1,
    const float* __restrict__ Wm2, const float* __restrict__ bm2,
    const float* __restrict__ Wl,  const float* __restrict__ bl) {

    __shared__ float sw[4096];        // current section weights 64x64
    __shared__ float sx[64 * 68];     // x tile transposed: sx[k][m], padded

    int t   = threadIdx.x;
    int pt0 = blockIdx.x * 64;

    for (int i = t; i < 4096; i += 256) {
        int r = i >> 6, c = i & 63;
        sx[c * 68 + r] = __ldg(x + (pt0 + r) * 64 + c);
    }

    int m0 = (t & 15) * 4;
    int n0 = (t >> 4) * 4;

    for (int sect = 0; sect < 5; sect++) {
        __syncthreads();
        for (int i = t; i < 4096; i += 256) {
            float v;
            if      (sect == 0) v = __ldg(Wf + i)        - __ldg(Wf + 8192 + i);
            else if (sect == 1) v = __ldg(Wf + 4096 + i) + __ldg(Wf + 8192 + i);
            else if (sect == 2) v = __ldg(Wm1 + 4096 + i);
            else if (sect == 3) v = __ldg(Wm2 + 8192 + i);
            else                v = __ldg(Wl + 12288 + i);
            sw[i] = v;
        }
        __syncthreads();

        float acc[4][4];
#pragma unroll
        for (int a = 0; a < 4; a++)
#pragma unroll
            for (int bq = 0; bq < 4; bq++) acc[a][bq] = 0.0f;

#pragma unroll 4
        for (int k = 0; k < 64; k++) {
            float4 av = *(const float4*)(sx + k * 68 + m0);
            float4 wv = *(const float4*)(sw + k * 64 + n0);
            float aa[4] = {av.x, av.y, av.z, av.w};
            float ww[4] = {wv.x, wv.y, wv.z, wv.w};
#pragma unroll
            for (int mi = 0; mi < 4; mi++)
#pragma unroll
                for (int ni = 0; ni < 4; ni++)
                    acc[mi][ni] = fmaf(aa[mi], ww[ni], acc[mi][ni]);
        }

        float4 bb = make_float4(0.f, 0.f, 0.f, 0.f);
        const float* bp = (sect == 0) ? bf : (sect == 2) ? bm1
                         : (sect == 3) ? bm2 : (sect == 4) ? bl : nullptr;
        if (bp) bb = __ldg((const float4*)(bp + n0));

#pragma unroll
        for (int mi = 0; mi < 4; mi++) {
            int pt = pt0 + m0 + mi;
            float4 o = make_float4(acc[mi][0] + bb.x, acc[mi][1] + bb.y,
                                   acc[mi][2] + bb.z, acc[mi][3] + bb.w);
            float* dst;
            if (sect == 1) dst = g_Q + pt * 64 + n0;
            else {
                int off = (sect == 0) ? 0 : (sect == 2) ? 64 : (sect == 3) ? 128 : 192;
                dst = g_L + pt * 256 + off + n0;
            }
            *(float4*)dst = o;
        }
    }
}

// ---------------------------------------------------------------------------
// Main edge-MLP + max kernel (scalar fp32 — proven version).
// ---------------------------------------------------------------------------
template <int KD>
__device__ __forceinline__ void gemm_acc(const float* __restrict__ a,
                                         const float* __restrict__ w,
                                         int m0, int n0, float acc[8][4]) {
#pragma unroll 4
    for (int k = 0; k < KD; k++) {
        float4 a0 = *(const float4*)(a + k * PAD + m0);
        float4 a1 = *(const float4*)(a + k * PAD + m0 + 4);
        float4 wv = *(const float4*)(w + k * 64 + n0);
        float av[8] = {a0.x, a0.y, a0.z, a0.w, a1.x, a1.y, a1.z, a1.w};
        float ww[4] = {wv.x, wv.y, wv.z, wv.w};
#pragma unroll
        for (int mi = 0; mi < 8; mi++)
#pragma unroll
            for (int ni = 0; ni < 4; ni++)
                acc[mi][ni] = fmaf(av[mi], ww[ni], acc[mi][ni]);
    }
}

__device__ __forceinline__ void store_relu_t(const float acc[8][4], float4 r,
                                             float* dstBase, int m0, int n0) {
    float rr[4] = {r.x, r.y, r.z, r.w};
#pragma unroll
    for (int ni = 0; ni < 4; ni++) {
        float4 lo = make_float4(fmaxf(acc[0][ni] + rr[ni], 0.f),
                                fmaxf(acc[1][ni] + rr[ni], 0.f),
                                fmaxf(acc[2][ni] + rr[ni], 0.f),
                                fmaxf(acc[3][ni] + rr[ni], 0.f));
        float4 hi = make_float4(fmaxf(acc[4][ni] + rr[ni], 0.f),
                                fmaxf(acc[5][ni] + rr[ni], 0.f),
                                fmaxf(acc[6][ni] + rr[ni], 0.f),
                                fmaxf(acc[7][ni] + rr[ni], 0.f));
        *(float4*)(dstBase + (n0 + ni) * PAD + m0)     = lo;
        *(float4*)(dstBase + (n0 + ni) * PAD + m0 + 4) = hi;
    }
}

__global__ __launch_bounds__(256, 1) void edge_mlp_kernel(
    const float* __restrict__ x,
    const float* __restrict__ Wm1,  // uses first 64 rows (4096 floats)
    const float* __restrict__ Wm2,  // uses first 128 rows (8192 floats)
    const float* __restrict__ Wl,   // uses first 192 rows (12288 floats)
    float* __restrict__ out) {

    extern __shared__ float smem[];
    float* s_w  = smem;                       // 24576 floats
    float* s_h  = smem + MAIN_W_FLOATS;       // 192*PAD floats
    int*   s_id = (int*)(smem + MAIN_W_FLOATS + MAIN_H_FLOATS);  // 128 ints

    int t = threadIdx.x;

    for (int i = t; i < 1024; i += 256)
        ((float4*)s_w)[i] = __ldg((const float4*)Wm1 + i);
    for (int i = t; i < 2048; i += 256)
        ((float4*)(s_w + 4096))[i] = __ldg((const float4*)Wm2 + i);
    for (int i = t; i < 3072; i += 256)
        ((float4*)(s_w + 12288))[i] = __ldg((const float4*)Wl + i);
    __syncthreads();

    const int m0 = (t & 15) * 8;       // 8 edges per thread
    const int n0 = (t >> 4) * 4;       // 4 output channels per thread
    const int p_local = (t & 15) >> 1; // point owning this thread's edges

    for (int g = blockIdx.x; g < NGROUPS; g += gridDim.x) {
        int ptg0 = g * 8;
        int b    = ptg0 >> 12;

        if (t < 128) s_id[t] = g_idx[ptg0 * KNN + t];
        __syncthreads();

        // ---- Gather: H1[c][m] = relu(P[pt][c] + Q[nbr][c]) ----
        for (int i = t; i < 2048; i += 256) {
            int m  = i & 127;
            int cq = i >> 7;
            int j  = s_id[m];
            int pt = ptg0 + (m >> 4);
            float4 qv = __ldg((const float4*)(g_Q + ((b << 12) + j) * 64 + cq * 4));
            float4 pv = __ldg((const float4*)(g_L + pt * 256 + cq * 4));
            float* hb = s_h + (128 + cq * 4) * PAD + m;
            hb[0 * PAD] = fmaxf(pv.x + qv.x, 0.f);
            hb[1 * PAD] = fmaxf(pv.y + qv.y, 0.f);
            hb[2 * PAD] = fmaxf(pv.z + qv.z, 0.f);
            hb[3 * PAD] = fmaxf(pv.w + qv.w, 0.f);
        }
        __syncthreads();

        int ptg = ptg0 + p_local;

        // ---- Step 2: H2 = relu(H1 @ Ws2 + R1) ----
        {
            float acc[8][4];
#pragma unroll
            for (int a = 0; a < 8; a++)
#pragma unroll
                for (int bq = 0; bq < 4; bq++) acc[a][bq] = 0.f;
            gemm_acc<64>(s_h + 128 * PAD, s_w, m0, n0, acc);
            float4 r = __ldg((const float4*)(g_L + ptg * 256 + 64 + n0));
            store_relu_t(acc, r, s_h + 64 * PAD, m0, n0);
        }
        __syncthreads();

        // ---- Step 3: H3 = relu([H2|H1] @ Ws3 + R2) ----
        {
            float acc[8][4];
#pragma unroll
            for (int a = 0; a < 8; a++)
#pragma unroll
                for (int bq = 0; bq < 4; bq++) acc[a][bq] = 0.f;
            gemm_acc<128>(s_h + 64 * PAD, s_w + 4096, m0, n0, acc);
            float4 r = __ldg((const float4*)(g_L + ptg * 256 + 128 + n0));
            store_relu_t(acc, r, s_h, m0, n0);
        }
        __syncthreads();

        // ---- Step 4: H4 = [H3|H2|H1] @ Ws4 + R3 (no relu), fused max over K ----
        {
            float acc[8][4];
#pragma unroll
            for (int a = 0; a < 8; a++)
#pragma unroll
                for (int bq = 0; bq < 4; bq++) acc[a][bq] = 0.f;
            gemm_acc<192>(s_h, s_w + 12288, m0, n0, acc);
            float4 r3 = __ldg((const float4*)(g_L + ptg * 256 + 192 + n0));
            float vmax[4];
#pragma unroll
            for (int ni = 0; ni < 4; ni++) {
                float v = acc[0][ni];
#pragma unroll
                for (int mi = 1; mi < 8; mi++) v = fmaxf(v, acc[mi][ni]);
                vmax[ni] = v;
            }
            vmax[0] += r3.x; vmax[1] += r3.y; vmax[2] += r3.z; vmax[3] += r3.w;
#pragma unroll
            for (int ni = 0; ni < 4; ni++)
                vmax[ni] = fmaxf(vmax[ni], __shfl_xor_sync(0xffffffffu, vmax[ni], 1));
            if ((t & 1) == 0)
                *(float4*)(out + ptg * 320 + n0) =
                    make_float4(vmax[0], vmax[1], vmax[2], vmax[3]);
        }

        // ---- Max over K for H3/H2/H1 directly from smem ----
        for (int i = t; i < 1536; i += 256) {
            int p   = i / 192;
            int row = i - p * 192;
            const float* hp = s_h + row * PAD + p * 16;
            float v = hp[0];
#pragma unroll
            for (int k2 = 1; k2 < 16; k2++) v = fmaxf(v, hp[k2]);
            out[(ptg0 + p) * 320 + 64 + row] = v;
        }

        // ---- x passthrough ----
        for (int i = t; i < 512; i += 256) {
            int p = i >> 6, c = i & 63;
            out[(ptg0 + p) * 320 + 256 + c] = __ldg(x + (ptg0 + p) * 64 + c);
        }
        __syncthreads();
    }
}

// ---------------------------------------------------------------------------
extern "C" void kernel_launch(void* const* d_in, const int* in_sizes, int n_in,
                              void* d_out, int out_size) {
    const float* x   = (const float*)d_in[0];
    const float* pos = (const float*)d_in[1];
    const float* Wf  = (const float*)d_in[2];
    const float* bf  = (const float*)d_in[3];
    const float* Wm1 = (const float*)d_in[4];
    const float* bm1 = (const float*)d_in[5];
    const float* Wm2 = (const float*)d_in[6];
    const float* bm2 = (const float*)d_in[7];
    const float* Wl  = (const float*)d_in[8];
    const float* bl  = (const float*)d_in[9];
    float* out = (float*)d_out;

    cudaFuncSetAttribute(knn_kernel,
                         cudaFuncAttributeMaxDynamicSharedMemorySize,
                         KNN_SMEM_BYTES);
    cudaFuncSetAttribute(edge_mlp_kernel,
                         cudaFuncAttributeMaxDynamicSharedMemorySize,
                         MAIN_SMEM_BYTES);

    knn_kernel<<<TOTPTS / QPB, 256, KNN_SMEM_BYTES>>>(pos);
    pre_kernel<<<256, 256>>>(x, Wf, bf, Wm1, bm1, Wm2, bm2, Wl, bl);
    edge_mlp_kernel<<<148, 256, MAIN_SMEM_BYTES>>>(x, Wm1, Wm2, Wl, out);
}

// round 9
// speedup vs baseline: 3.0414x; 1.9965x over previous
#include <cuda_runtime.h>
#include <cuda_bf16.h>
#include <cstdint>

#define TOTPTS 16384
#define NPTS   4096
#define KNN    16

// ---- knn config (unchanged winner) ----
#define QPB  32
#define TILE 256
#define KNN_SMEM_BYTES (TILE * 16 + QPB * TILE * 4 + QPB * KNN * 4 * 2 + QPB * 8)

// ---- edge_mlp smem layout (bytes) ----
// W: [n=64][k=384] bf16, stride 392 elem (784B). cols 0..63 Ws2, 64..191 Ws3, 192..383 Ws4.
// A: [m=128][k=192] bf16, stride 200 elem (400B). cols 0..63 H3, 64..127 H2, 128..191 H1.
#define WBYTES  50176            // 64*392*2
#define ABYTES  51200            // 128*200*2
#define SM_W_HI 0
#define SM_W_LO 50176
#define SM_A_HI 100352
#define SM_A_LO 151552
#define SM_R    202752           // 8 warps x 192 floats = 6144 B
#define MAIN_SMEM_BYTES 208896

// Scratch (allocation-free rule: device globals)
__device__ __align__(16) float g_L[TOTPTS * 256];   // [P | R1 | R2 | R3] per point
__device__ __align__(16) float g_Q[TOTPTS * 64];    // Q per point
__device__ int g_idx[TOTPTS * KNN];
__device__ __align__(16) unsigned char g_Wpk[100352]; // packed bf16 hi(50176)+lo(50176)

// ===================== helpers =====================
__device__ __forceinline__ uint32_t smem_to_u32(const void* p) {
    uint32_t a;
    asm("{ .reg .u64 t; cvta.to.shared.u64 t, %1; cvt.u32.u64 %0, t; }" : "=r"(a) : "l"(p));
    return a;
}
#define LDSM4(r0, r1, r2, r3, addr) \
    asm volatile("ldmatrix.sync.aligned.m8n8.x4.shared.b16 {%0,%1,%2,%3}, [%4];" \
        : "=r"(r0), "=r"(r1), "=r"(r2), "=r"(r3) : "r"(addr))
#define LDSM2(r0, r1, addr) \
    asm volatile("ldmatrix.sync.aligned.m8n8.x2.shared.b16 {%0,%1}, [%2];" \
        : "=r"(r0), "=r"(r1) : "r"(addr))
#define MMA16816(c, a0, a1, a2, a3, b0, b1) \
    asm volatile("mma.sync.aligned.m16n8k16.row.col.f32.bf16.bf16.f32 " \
        "{%0,%1,%2,%3}, {%4,%5,%6,%7}, {%8,%9}, {%0,%1,%2,%3};" \
        : "+f"((c)[0]), "+f"((c)[1]), "+f"((c)[2]), "+f"((c)[3]) \
        : "r"(a0), "r"(a1), "r"(a2), "r"(a3), "r"(b0), "r"(b1))

__device__ __forceinline__ void hilo2(float a, float b, uint32_t& h, uint32_t& l) {
    __nv_bfloat16 ha = __float2bfloat16(a), hb = __float2bfloat16(b);
    float ra = a - __bfloat162float(ha), rb = b - __bfloat162float(hb);
    __nv_bfloat162 H; H.x = ha; H.y = hb;
    __nv_bfloat162 L; L.x = __float2bfloat16(ra); L.y = __float2bfloat16(rb);
    h = *(uint32_t*)&H; l = *(uint32_t*)&L;
}

// ---------------------------------------------------------------------------
// KNN v5 (unchanged winner)
// ---------------------------------------------------------------------------
__global__ __launch_bounds__(256) void knn_kernel(const float* __restrict__ pos) {
    extern __shared__ char kshm[];
    float4* sp    = (float4*)kshm;
    int*    bufI  = (int*)(kshm + TILE * 16);
    float*  seedD = (float*)(kshm + TILE * 16 + QPB * TILE * 4);
    int*    seedI = (int*)(kshm + TILE * 16 + QPB * TILE * 4 + QPB * KNN * 4);
    int*    scnt  = (int*)(kshm + TILE * 16 + QPB * TILE * 4 + QPB * KNN * 8);
    float*  stau  = (float*)(kshm + TILE * 16 + QPB * TILE * 4 + QPB * KNN * 8 + QPB * 4);

    int t   = threadIdx.x;
    int ql  = t >> 3;
    int sub = t & 7;
    int qg  = blockIdx.x * QPB + ql;
    int b   = qg >> 12;
    int q   = qg & 4095;
    const float* pb = pos + b * NPTS * 3;

    if (t < QPB) scnt[t] = 0;

    float qx = __ldg(pb + q * 3 + 0);
    float qy = __ldg(pb + q * 3 + 1);
    float qz = __ldg(pb + q * 3 + 2);
    float qn = qx * qx + qy * qy + qz * qz;

    float rqx = 0.f, rqy = 0.f, rqz = 0.f, rqn = 0.f;
    if (t < QPB) {
        int rq = (blockIdx.x * QPB + t) & 4095;
        rqx = __ldg(pb + rq * 3 + 0);
        rqy = __ldg(pb + rq * 3 + 1);
        rqz = __ldg(pb + rq * 3 + 2);
        rqn = rqx * rqx + rqy * rqy + rqz * rqz;
    }

    float s0 = 3.0e38f, s1 = 3.0e38f;
    int   i0 = 0,       i1 = 0;

    for (int t0 = 0; t0 < NPTS; t0 += TILE) {
        __syncthreads();
        {
            int j = t0 + t;
            float x = pb[j * 3 + 0], y = pb[j * 3 + 1], z = pb[j * 3 + 2];
            sp[t] = make_float4(x, y, z, x * x + y * y + z * z);
        }
        __syncthreads();
#pragma unroll 8
        for (int jj = 0; jj < TILE / 8; jj++) {
            int jl = sub + (jj << 3);
            float4 c = sp[jl];
            float dot = qx * c.x;
            dot = fmaf(qy, c.y, dot);
            dot = fmaf(qz, c.z, dot);
            float d2 = fmaf(dot, -2.0f, qn + c.w);
            int jg = t0 + jl;
            if (d2 < s1 && jg != q) {
                if (d2 < s0) { s1 = s0; i1 = i0; s0 = d2; i0 = jg; }
                else         { s1 = d2; i1 = jg; }
            }
        }
    }
    seedD[ql * KNN + sub * 2 + 0] = s0;
    seedI[ql * KNN + sub * 2 + 0] = i0;
    seedD[ql * KNN + sub * 2 + 1] = s1;
    seedI[ql * KNN + sub * 2 + 1] = i1;
    __syncthreads();

    float dv[KNN];
    int   iv[KNN];
    float dmax = 0.f;
    int   amax = 0;
    if (t < QPB) {
#pragma unroll
        for (int r = 0; r < KNN; r++) {
            dv[r] = seedD[t * KNN + r];
            iv[r] = seedI[t * KNN + r];
        }
        dmax = dv[0]; amax = 0;
#pragma unroll
        for (int r = 1; r < KNN; r++)
            if (dv[r] > dmax) { dmax = dv[r]; amax = r; }
        stau[t] = dmax;
    }

    for (int t0 = 0; t0 < NPTS; t0 += TILE) {
        __syncthreads();
        {
            int j = t0 + t;
            float x = pb[j * 3 + 0], y = pb[j * 3 + 1], z = pb[j * 3 + 2];
            sp[t] = make_float4(x, y, z, x * x + y * y + z * z);
        }
        __syncthreads();

        float tau = stau[ql];
        int*  bI  = bufI + ql * TILE;

#pragma unroll 8
        for (int jj = 0; jj < TILE / 8; jj++) {
            int jl = sub + (jj << 3);
            float4 c = sp[jl];
            float dot = qx * c.x;
            dot = fmaf(qy, c.y, dot);
            dot = fmaf(qz, c.z, dot);
            float d2 = fmaf(dot, -2.0f, qn + c.w);
            int jg = t0 + jl;
            if (d2 < tau && jg != q) {
                int slot = atomicAdd(&scnt[ql], 1);
                bI[slot] = jl;
            }
        }
        __syncthreads();

        if (t < QPB) {
            int n = scnt[t];
            const int* rI = bufI + t * TILE;
            for (int e = 0; e < n; e++) {
                int jl = rI[e];
                float4 c = sp[jl];
                float dot = rqx * c.x;
                dot = fmaf(rqy, c.y, dot);
                dot = fmaf(rqz, c.z, dot);
                float d2 = fmaf(dot, -2.0f, rqn + c.w);
                if (d2 < dmax) {
                    int jg = t0 + jl;
                    bool dup = false;
#pragma unroll
                    for (int r = 0; r < KNN; r++) dup = dup || (iv[r] == jg);
                    if (!dup) {
                        dv[amax] = d2; iv[amax] = jg;
                        dmax = dv[0]; amax = 0;
#pragma unroll
                        for (int r = 1; r < KNN; r++)
                            if (dv[r] > dmax) { dmax = dv[r]; amax = r; }
                    }
                }
            }
            scnt[t] = 0;
            stau[t] = dmax;
        }
    }

    if (t < QPB) {
        int obase = (blockIdx.x * QPB + t) * KNN;
#pragma unroll
        for (int r = 0; r < KNN; r++) g_idx[obase + r] = iv[r];
    }
}

// ---------------------------------------------------------------------------
// Per-point precompute (unchanged)
// ---------------------------------------------------------------------------
__global__ __launch_bounds__(256) void pre_kernel(
    const float* __restrict__ x,
    const float* __restrict__ Wf,  const float* __restrict__ bf,
    const float* __restrict__ Wm1, const float* __restrict__ bm1,
    const float* __restrict__ Wm2, const float* __restrict__ bm2,
    const float* __restrict__ Wl,  const float* __restrict__ bl) {

    __shared__ float sw[4096];
    __shared__ float sx[64 * 68];

    int t   = threadIdx.x;
    int pt0 = blockIdx.x * 64;

    for (int i = t; i < 4096; i += 256) {
        int r = i >> 6, c = i & 63;
        sx[c * 68 + r] = __ldg(x + (pt0 + r) * 64 + c);
    }

    int m0 = (t & 15) * 4;
    int n0 = (t >> 4) * 4;

    for (int sect = 0; sect < 5; sect++) {
        __syncthreads();
        for (int i = t; i < 4096; i += 256) {
            float v;
            if      (sect == 0) v = __ldg(Wf + i)        - __ldg(Wf + 8192 + i);
            else if (sect == 1) v = __ldg(Wf + 4096 + i) + __ldg(Wf + 8192 + i);
            else if (sect == 2) v = __ldg(Wm1 + 4096 + i);
            else if (sect == 3) v = __ldg(Wm2 + 8192 + i);
            else                v = __ldg(Wl + 12288 + i);
            sw[i] = v;
        }
        __syncthreads();

        float acc[4][4];
#pragma unroll
        for (int a = 0; a < 4; a++)
#pragma unroll
            for (int bq = 0; bq < 4; bq++) acc[a][bq] = 0.0f;

#pragma unroll 4
        for (int k = 0; k < 64; k++) {
            float4 av = *(const float4*)(sx + k * 68 + m0);
            float4 wv = *(const float4*)(sw + k * 64 + n0);
            float aa[4] = {av.x, av.y, av.z, av.w};
            float ww[4] = {wv.x, wv.y, wv.z, wv.w};
#pragma unroll
            for (int mi = 0; mi < 4; mi++)
#pragma unroll
                for (int ni = 0; ni < 4; ni++)
                    acc[mi][ni] = fmaf(aa[mi], ww[ni], acc[mi][ni]);
        }

        float4 bb = make_float4(0.f, 0.f, 0.f, 0.f);
        const float* bp = (sect == 0) ? bf : (sect == 2) ? bm1
                         : (sect == 3) ? bm2 : (sect == 4) ? bl : nullptr;
        if (bp) bb = __ldg((const float4*)(bp + n0));

#pragma unroll
        for (int mi = 0; mi < 4; mi++) {
            int pt = pt0 + m0 + mi;
            float4 o = make_float4(acc[mi][0] + bb.x, acc[mi][1] + bb.y,
                                   acc[mi][2] + bb.z, acc[mi][3] + bb.w);
            float* dst;
            if (sect == 1) dst = g_Q + pt * 64 + n0;
            else {
                int off = (sect == 0) ? 0 : (sect == 2) ? 64 : (sect == 3) ? 128 : 192;
                dst = g_L + pt * 256 + off + n0;
            }
            *(float4*)dst = o;
        }
    }
}

// ---------------------------------------------------------------------------
// Weight repack: [n=64][k] row-major bf16 hi/lo, k-concat Ws2|Ws3|Ws4, stride 392.
// ---------------------------------------------------------------------------
__global__ __launch_bounds__(256) void init_w_kernel(
    const float* __restrict__ Wm1, const float* __restrict__ Wm2,
    const float* __restrict__ Wl) {
    int e = blockIdx.x * 256 + threadIdx.x;          // 0..24575
    const float* src; int colbase;
    if (e < 4096)       { src = Wm1; colbase = 0; }
    else if (e < 12288) { src = Wm2; colbase = 64;  e -= 4096; }
    else                { src = Wl;  colbase = 192; e -= 12288; }
    int k = e >> 6, n = e & 63;
    float v = src[k * 64 + n];
    __nv_bfloat16 h = __float2bfloat16(v);
    __nv_bfloat16 l = __float2bfloat16(v - __bfloat162float(h));
    uint32_t off = (uint32_t)(n * 392 + colbase + k) * 2;
    *(__nv_bfloat16*)(g_Wpk + off)         = h;
    *(__nv_bfloat16*)(g_Wpk + 50176 + off) = l;
}

// ---------------------------------------------------------------------------
// One layer: NK k-steps of m16n8k16, 8 n-tiles, 3 passes (hh, hl, lh).
// aH/aL: this lane's ldmatrix A address (layer k-offset applied).
// bH/bL: this lane's ldmatrix B address (layer k-offset applied).
// ---------------------------------------------------------------------------
template <int NK>
__device__ __forceinline__ void run_layer(
    uint32_t aH, uint32_t aL, uint32_t bH, uint32_t bL, float acc[8][4]) {
#pragma unroll
    for (int s = 0; s < NK / 16; s++) {
        uint32_t ah0, ah1, ah2, ah3, al0, al1, al2, al3;
        LDSM4(ah0, ah1, ah2, ah3, aH + s * 32);
        LDSM4(al0, al1, al2, al3, aL + s * 32);
        uint32_t bh[8][2], bl[8][2];
#pragma unroll
        for (int nt = 0; nt < 8; nt++) {
            LDSM2(bh[nt][0], bh[nt][1], bH + nt * (8 * 784) + s * 32);
            LDSM2(bl[nt][0], bl[nt][1], bL + nt * (8 * 784) + s * 32);
        }
#pragma unroll
        for (int nt = 0; nt < 8; nt++)
            MMA16816(acc[nt], ah0, ah1, ah2, ah3, bh[nt][0], bh[nt][1]);
#pragma unroll
        for (int nt = 0; nt < 8; nt++)
            MMA16816(acc[nt], ah0, ah1, ah2, ah3, bl[nt][0], bl[nt][1]);
#pragma unroll
        for (int nt = 0; nt < 8; nt++)
            MMA16816(acc[nt], al0, al1, al2, al3, bh[nt][0], bh[nt][1]);
    }
}

// Epilogue: +R, optional relu, optional hi/lo store to A dest cols, max over
// the warp's 16 edges, write out[p*320 + obase .. +64].
__device__ __forceinline__ void epilogue(
    float acc[8][4], const float* sRw, int layer, bool do_relu, bool storeA,
    int destcol, char* sAh, char* sAl, int w,
    float* __restrict__ out, int p, int obase, int lane) {
    int tg = lane >> 2, tc = lane & 3;
#pragma unroll
    for (int nt = 0; nt < 8; nt++) {
        int n0 = nt * 8 + 2 * tc;
        float r0 = sRw[layer * 64 + n0], r1 = sRw[layer * 64 + n0 + 1];
        float c0 = acc[nt][0] + r0, c1 = acc[nt][1] + r1;
        float c2 = acc[nt][2] + r0, c3 = acc[nt][3] + r1;
        if (do_relu) {
            c0 = fmaxf(c0, 0.f); c1 = fmaxf(c1, 0.f);
            c2 = fmaxf(c2, 0.f); c3 = fmaxf(c3, 0.f);
        }
        if (storeA) {
            uint32_t h, l;
            char* r0p = sAh + (w * 16 + tg) * 400 + (destcol + n0) * 2;
            char* l0p = sAl + (w * 16 + tg) * 400 + (destcol + n0) * 2;
            hilo2(c0, c1, h, l);
            *(uint32_t*)r0p = h; *(uint32_t*)l0p = l;
            hilo2(c2, c3, h, l);
            *(uint32_t*)(r0p + 8 * 400) = h; *(uint32_t*)(l0p + 8 * 400) = l;
        }
        float m0 = fmaxf(c0, c2), m1 = fmaxf(c1, c3);
        m0 = fmaxf(m0, __shfl_xor_sync(0xffffffffu, m0, 4));
        m0 = fmaxf(m0, __shfl_xor_sync(0xffffffffu, m0, 8));
        m0 = fmaxf(m0, __shfl_xor_sync(0xffffffffu, m0, 16));
        m1 = fmaxf(m1, __shfl_xor_sync(0xffffffffu, m1, 4));
        m1 = fmaxf(m1, __shfl_xor_sync(0xffffffffu, m1, 8));
        m1 = fmaxf(m1, __shfl_xor_sync(0xffffffffu, m1, 16));
        if (tg == 0)
            *(float2*)(out + p * 320 + obase + n0) = make_float2(m0, m1);
    }
}

// ---------------------------------------------------------------------------
// Main edge-MLP: one warp = one point (16 edges = one m16 tile). No block
// syncs in the mainloop — only warp-local dependencies.
// ---------------------------------------------------------------------------
__global__ __launch_bounds__(256, 1) void edge_mlp_kernel(
    const float* __restrict__ x, float* __restrict__ out) {

    extern __shared__ char sm[];
    char*  sAh = sm + SM_A_HI;
    char*  sAl = sm + SM_A_LO;
    float* sR  = (float*)(sm + SM_R);

    int t = threadIdx.x, lane = t & 31, w = t >> 5;

    // stage packed weights (hi+lo, 100352 B)
    for (int i = t; i < 100352 / 16; i += 256)
        ((uint4*)sm)[i] = __ldg((const uint4*)g_Wpk + i);
    __syncthreads();

    uint32_t smb = smem_to_u32(sm);
    int ar = lane & 15, ach = lane >> 4;
    uint32_t aH = smb + SM_A_HI + (w * 16 + ar) * 400 + ach * 16;
    uint32_t aL = aH + ABYTES;
    int bn = lane & 7, bkh = (lane >> 3) & 1;
    uint32_t bH = smb + SM_W_HI + bn * 784 + bkh * 16;
    uint32_t bL = bH + WBYTES;
    float* sRw = sR + w * 192;

    for (int p = blockIdx.x * 8 + w; p < TOTPTS; p += 148 * 8) {
        int b = p >> 12;

        // ---- Gather: H1 = relu(P_p + Q_j) -> A cols 128..191 + fused H1 max ----
        {
            int e = lane >> 1, half = lane & 1, c0 = half << 5;
            int j = __ldg(g_idx + p * KNN + e);
            const float4* Pr = (const float4*)(g_L + p * 256 + c0);
            const float4* Qr = (const float4*)(g_Q + ((b << 12) + j) * 64 + c0);
            float v[32];
#pragma unroll
            for (int i = 0; i < 8; i++) {
                float4 pv = __ldg(Pr + i);
                float4 qv = __ldg(Qr + i);
                v[4 * i + 0] = fmaxf(pv.x + qv.x, 0.f);
                v[4 * i + 1] = fmaxf(pv.y + qv.y, 0.f);
                v[4 * i + 2] = fmaxf(pv.z + qv.z, 0.f);
                v[4 * i + 3] = fmaxf(pv.w + qv.w, 0.f);
            }
            char* rowH = sAh + (w * 16 + e) * 400 + (128 + c0) * 2;
            char* rowL = sAl + (w * 16 + e) * 400 + (128 + c0) * 2;
#pragma unroll
            for (int i = 0; i < 16; i++) {
                uint32_t h, l;
                hilo2(v[2 * i], v[2 * i + 1], h, l);
                *(uint32_t*)(rowH + 4 * i) = h;
                *(uint32_t*)(rowL + 4 * i) = l;
            }
            // H1 max over 16 edges (edge index in lane bits 1..4)
#pragma unroll
            for (int i = 0; i < 32; i++) {
                float mv = v[i];
                mv = fmaxf(mv, __shfl_xor_sync(0xffffffffu, mv, 2));
                mv = fmaxf(mv, __shfl_xor_sync(0xffffffffu, mv, 4));
                mv = fmaxf(mv, __shfl_xor_sync(0xffffffffu, mv, 8));
                mv = fmaxf(mv, __shfl_xor_sync(0xffffffffu, mv, 16));
                v[i] = mv;
            }
            if (lane < 2) {
                float* dst = out + p * 320 + 192 + c0;
#pragma unroll
                for (int i = 0; i < 32; i += 4)
                    *(float4*)(dst + i) = make_float4(v[i], v[i + 1], v[i + 2], v[i + 3]);
            }
            // stage R1,R2,R3 (192 floats) for this point
            for (int i = lane; i < 192; i += 32)
                sRw[i] = __ldg(g_L + p * 256 + 64 + i);
            // x passthrough (cols 256..320)
            float2 xv = *(const float2*)(x + p * 64 + lane * 2);
            *(float2*)(out + p * 320 + 256 + lane * 2) = xv;
        }
        __syncwarp();

        float acc[8][4];

        // ---- Layer 2: H2 = relu(H1 @ Ws2 + R1); A k-off 128, B k-off 0 ----
#pragma unroll
        for (int i = 0; i < 8; i++)
#pragma unroll
            for (int q2 = 0; q2 < 4; q2++) acc[i][q2] = 0.f;
        run_layer<64>(aH + 256, aL + 256, bH, bL, acc);
        epilogue(acc, sRw, 0, true, true, 64, sAh, sAl, w, out, p, 128, lane);
        __syncwarp();

        // ---- Layer 3: H3 = relu([H2|H1] @ Ws3 + R2); A k-off 64, B k-off 64 ----
#pragma unroll
        for (int i = 0; i < 8; i++)
#pragma unroll
            for (int q2 = 0; q2 < 4; q2++) acc[i][q2] = 0.f;
        run_layer<128>(aH + 128, aL + 128, bH + 128, bL + 128, acc);
        epilogue(acc, sRw, 1, true, true, 0, sAh, sAl, w, out, p, 64, lane);
        __syncwarp();

        // ---- Layer 4: H4 = [H3|H2|H1] @ Ws4 + R3 (no relu); A k-off 0, B k-off 192 ----
#pragma unroll
        for (int i = 0; i < 8; i++)
#pragma unroll
            for (int q2 = 0; q2 < 4; q2++) acc[i][q2] = 0.f;
        run_layer<192>(aH, aL, bH + 384, bL + 384, acc);
        epilogue(acc, sRw, 2, false, false, 0, sAh, sAl, w, out, p, 0, lane);
        __syncwarp();
    }
}

// ---------------------------------------------------------------------------
extern "C" void kernel_launch(void* const* d_in, const int* in_sizes, int n_in,
                              void* d_out, int out_size) {
    const float* x   = (const float*)d_in[0];
    const float* pos = (const float*)d_in[1];
    const float* Wf  = (const float*)d_in[2];
    const float* bf  = (const float*)d_in[3];
    const float* Wm1 = (const float*)d_in[4];
    const float* bm1 = (const float*)d_in[5];
    const float* Wm2 = (const float*)d_in[6];
    const float* bm2 = (const float*)d_in[7];
    const float* Wl  = (const float*)d_in[8];
    const float* bl  = (const float*)d_in[9];
    float* out = (float*)d_out;

    cudaFuncSetAttribute(knn_kernel,
                         cudaFuncAttributeMaxDynamicSharedMemorySize,
                         KNN_SMEM_BYTES);
    cudaFuncSetAttribute(edge_mlp_kernel,
                         cudaFuncAttributeMaxDynamicSharedMemorySize,
                         MAIN_SMEM_BYTES);

    init_w_kernel<<<96, 256>>>(Wm1, Wm2, Wl);
    knn_kernel<<<TOTPTS / QPB, 256, KNN_SMEM_BYTES>>>(pos);
    pre_kernel<<<256, 256>>>(x, Wf, bf, Wm1, bm1, Wm2, bm2, Wl, bl);
    edge_mlp_kernel<<<148, 256, MAIN_SMEM_BYTES>>>(x, out);
}

// round 10
// speedup vs baseline: 3.3786x; 1.1109x over previous
#include <cuda_runtime.h>
#include <cuda_bf16.h>
#include <cstdint>

#define TOTPTS 16384
#define NPTS   4096
#define KNN    16

// ---- knn config (unchanged winner) ----
#define QPB  32
#define TILE 256
#define KNN_SMEM_BYTES (TILE * 16 + QPB * TILE * 4 + QPB * KNN * 4 * 2 + QPB * 8)

// ---- edge_mlp smem: weights only ----
// W: [n=64][k=384] bf16, stride 392 elem (784B). k-cols 0..63 Ws2, 64..191 Ws3, 192..383 Ws4.
#define WBYTES  50176            // 64*392*2
#define MAIN_SMEM_BYTES 100352   // hi + lo

// Scratch (allocation-free rule: device globals)
__device__ __align__(16) float g_L[TOTPTS * 256];   // [P | R1 | R2 | R3] per point
__device__ __align__(16) float g_Q[TOTPTS * 64];    // Q per point
__device__ int g_idx[TOTPTS * KNN];
__device__ __align__(16) unsigned char g_Wpk[100352]; // packed bf16 hi(50176)+lo(50176)

// ===================== helpers =====================
__device__ __forceinline__ uint32_t smem_to_u32(const void* p) {
    uint32_t a;
    asm("{ .reg .u64 t; cvta.to.shared.u64 t, %1; cvt.u32.u64 %0, t; }" : "=r"(a) : "l"(p));
    return a;
}
#define LDSM4(r0, r1, r2, r3, addr) \
    asm volatile("ldmatrix.sync.aligned.m8n8.x4.shared.b16 {%0,%1,%2,%3}, [%4];" \
        : "=r"(r0), "=r"(r1), "=r"(r2), "=r"(r3) : "r"(addr))
#define MMA16816(c, a0, a1, a2, a3, b0, b1) \
    asm volatile("mma.sync.aligned.m16n8k16.row.col.f32.bf16.bf16.f32 " \
        "{%0,%1,%2,%3}, {%4,%5,%6,%7}, {%8,%9}, {%0,%1,%2,%3};" \
        : "+f"((c)[0]), "+f"((c)[1]), "+f"((c)[2]), "+f"((c)[3]) \
        : "r"(a0), "r"(a1), "r"(a2), "r"(a3), "r"(b0), "r"(b1))

__device__ __forceinline__ void hilo2(float a, float b, uint32_t& h, uint32_t& l) {
    __nv_bfloat16 ha = __float2bfloat16(a), hb = __float2bfloat16(b);
    float ra = a - __bfloat162float(ha), rb = b - __bfloat162float(hb);
    __nv_bfloat162 H; H.x = ha; H.y = hb;
    __nv_bfloat162 L; L.x = __float2bfloat16(ra); L.y = __float2bfloat16(rb);
    h = *(uint32_t*)&H; l = *(uint32_t*)&L;
}

// ---------------------------------------------------------------------------
// KNN v5 (unchanged winner)
// ---------------------------------------------------------------------------
__global__ __launch_bounds__(256) void knn_kernel(const float* __restrict__ pos) {
    extern __shared__ char kshm[];
    float4* sp    = (float4*)kshm;
    int*    bufI  = (int*)(kshm + TILE * 16);
    float*  seedD = (float*)(kshm + TILE * 16 + QPB * TILE * 4);
    int*    seedI = (int*)(kshm + TILE * 16 + QPB * TILE * 4 + QPB * KNN * 4);
    int*    scnt  = (int*)(kshm + TILE * 16 + QPB * TILE * 4 + QPB * KNN * 8);
    float*  stau  = (float*)(kshm + TILE * 16 + QPB * TILE * 4 + QPB * KNN * 8 + QPB * 4);

    int t   = threadIdx.x;
    int ql  = t >> 3;
    int sub = t & 7;
    int qg  = blockIdx.x * QPB + ql;
    int b   = qg >> 12;
    int q   = qg & 4095;
    const float* pb = pos + b * NPTS * 3;

    if (t < QPB) scnt[t] = 0;

    float qx = __ldg(pb + q * 3 + 0);
    float qy = __ldg(pb + q * 3 + 1);
    float qz = __ldg(pb + q * 3 + 2);
    float qn = qx * qx + qy * qy + qz * qz;

    float rqx = 0.f, rqy = 0.f, rqz = 0.f, rqn = 0.f;
    if (t < QPB) {
        int rq = (blockIdx.x * QPB + t) & 4095;
        rqx = __ldg(pb + rq * 3 + 0);
        rqy = __ldg(pb + rq * 3 + 1);
        rqz = __ldg(pb + rq * 3 + 2);
        rqn = rqx * rqx + rqy * rqy + rqz * rqz;
    }

    float s0 = 3.0e38f, s1 = 3.0e38f;
    int   i0 = 0,       i1 = 0;

    for (int t0 = 0; t0 < NPTS; t0 += TILE) {
        __syncthreads();
        {
            int j = t0 + t;
            float x = pb[j * 3 + 0], y = pb[j * 3 + 1], z = pb[j * 3 + 2];
            sp[t] = make_float4(x, y, z, x * x + y * y + z * z);
        }
        __syncthreads();
#pragma unroll 8
        for (int jj = 0; jj < TILE / 8; jj++) {
            int jl = sub + (jj << 3);
            float4 c = sp[jl];
            float dot = qx * c.x;
            dot = fmaf(qy, c.y, dot);
            dot = fmaf(qz, c.z, dot);
            float d2 = fmaf(dot, -2.0f, qn + c.w);
            int jg = t0 + jl;
            if (d2 < s1 && jg != q) {
                if (d2 < s0) { s1 = s0; i1 = i0; s0 = d2; i0 = jg; }
                else         { s1 = d2; i1 = jg; }
            }
        }
    }
    seedD[ql * KNN + sub * 2 + 0] = s0;
    seedI[ql * KNN + sub * 2 + 0] = i0;
    seedD[ql * KNN + sub * 2 + 1] = s1;
    seedI[ql * KNN + sub * 2 + 1] = i1;
    __syncthreads();

    float dv[KNN];
    int   iv[KNN];
    float dmax = 0.f;
    int   amax = 0;
    if (t < QPB) {
#pragma unroll
        for (int r = 0; r < KNN; r++) {
            dv[r] = seedD[t * KNN + r];
            iv[r] = seedI[t * KNN + r];
        }
        dmax = dv[0]; amax = 0;
#pragma unroll
        for (int r = 1; r < KNN; r++)
            if (dv[r] > dmax) { dmax = dv[r]; amax = r; }
        stau[t] = dmax;
    }

    for (int t0 = 0; t0 < NPTS; t0 += TILE) {
        __syncthreads();
        {
            int j = t0 + t;
            float x = pb[j * 3 + 0], y = pb[j * 3 + 1], z = pb[j * 3 + 2];
            sp[t] = make_float4(x, y, z, x * x + y * y + z * z);
        }
        __syncthreads();

        float tau = stau[ql];
        int*  bI  = bufI + ql * TILE;

#pragma unroll 8
        for (int jj = 0; jj < TILE / 8; jj++) {
            int jl = sub + (jj << 3);
            float4 c = sp[jl];
            float dot = qx * c.x;
            dot = fmaf(qy, c.y, dot);
            dot = fmaf(qz, c.z, dot);
            float d2 = fmaf(dot, -2.0f, qn + c.w);
            int jg = t0 + jl;
            if (d2 < tau && jg != q) {
                int slot = atomicAdd(&scnt[ql], 1);
                bI[slot] = jl;
            }
        }
        __syncthreads();

        if (t < QPB) {
            int n = scnt[t];
            const int* rI = bufI + t * TILE;
            for (int e = 0; e < n; e++) {
                int jl = rI[e];
                float4 c = sp[jl];
                float dot = rqx * c.x;
                dot = fmaf(rqy, c.y, dot);
                dot = fmaf(rqz, c.z, dot);
                float d2 = fmaf(dot, -2.0f, rqn + c.w);
                if (d2 < dmax) {
                    int jg = t0 + jl;
                    bool dup = false;
#pragma unroll
                    for (int r = 0; r < KNN; r++) dup = dup || (iv[r] == jg);
                    if (!dup) {
                        dv[amax] = d2; iv[amax] = jg;
                        dmax = dv[0]; amax = 0;
#pragma unroll
                        for (int r = 1; r < KNN; r++)
                            if (dv[r] > dmax) { dmax = dv[r]; amax = r; }
                    }
                }
            }
            scnt[t] = 0;
            stau[t] = dmax;
        }
    }

    if (t < QPB) {
        int obase = (blockIdx.x * QPB + t) * KNN;
#pragma unroll
        for (int r = 0; r < KNN; r++) g_idx[obase + r] = iv[r];
    }
}

// ---------------------------------------------------------------------------
// Per-point precompute (unchanged)
// ---------------------------------------------------------------------------
__global__ __launch_bounds__(256) void pre_kernel(
    const float* __restrict__ x,
    const float* __restrict__ Wf,  const float* __restrict__ bf,
    const float* __restrict__ Wm1, const float* __restrict__ bm1,
    const float* __restrict__ Wm2, const float* __restrict__ bm2,
    const float* __restrict__ Wl,  const float* __restrict__ bl) {

    __shared__ float sw[4096];
    __shared__ float sx[64 * 68];

    int t   = threadIdx.x;
    int pt0 = blockIdx.x * 64;

    for (int i = t; i < 4096; i += 256) {
        int r = i >> 6, c = i & 63;
        sx[c * 68 + r] = __ldg(x + (pt0 + r) * 64 + c);
    }

    int m0 = (t & 15) * 4;
    int n0 = (t >> 4) * 4;

    for (int sect = 0; sect < 5; sect++) {
        __syncthreads();
        for (int i = t; i < 4096; i += 256) {
            float v;
            if      (sect == 0) v = __ldg(Wf + i)        - __ldg(Wf + 8192 + i);
            else if (sect == 1) v = __ldg(Wf + 4096 + i) + __ldg(Wf + 8192 + i);
            else if (sect == 2) v = __ldg(Wm1 + 4096 + i);
            else if (sect == 3) v = __ldg(Wm2 + 8192 + i);
            else                v = __ldg(Wl + 12288 + i);
            sw[i] = v;
        }
        __syncthreads();

        float acc[4][4];
#pragma unroll
        for (int a = 0; a < 4; a++)
#pragma unroll
            for (int bq = 0; bq < 4; bq++) acc[a][bq] = 0.0f;

#pragma unroll 4
        for (int k = 0; k < 64; k++) {
            float4 av = *(const float4*)(sx + k * 68 + m0);
            float4 wv = *(const float4*)(sw + k * 64 + n0);
            float aa[4] = {av.x, av.y, av.z, av.w};
            float ww[4] = {wv.x, wv.y, wv.z, wv.w};
#pragma unroll
            for (int mi = 0; mi < 4; mi++)
#pragma unroll
                for (int ni = 0; ni < 4; ni++)
                    acc[mi][ni] = fmaf(aa[mi], ww[ni], acc[mi][ni]);
        }

        float4 bb = make_float4(0.f, 0.f, 0.f, 0.f);
        const float* bp = (sect == 0) ? bf : (sect == 2) ? bm1
                         : (sect == 3) ? bm2 : (sect == 4) ? bl : nullptr;
        if (bp) bb = __ldg((const float4*)(bp + n0));

#pragma unroll
        for (int mi = 0; mi < 4; mi++) {
            int pt = pt0 + m0 + mi;
            float4 o = make_float4(acc[mi][0] + bb.x, acc[mi][1] + bb.y,
                                   acc[mi][2] + bb.z, acc[mi][3] + bb.w);
            float* dst;
            if (sect == 1) dst = g_Q + pt * 64 + n0;
            else {
                int off = (sect == 0) ? 0 : (sect == 2) ? 64 : (sect == 3) ? 128 : 192;
                dst = g_L + pt * 256 + off + n0;
            }
            *(float4*)dst = o;
        }
    }
}

// ---------------------------------------------------------------------------
// Weight repack: [n=64][k] row-major bf16 hi/lo, k-concat Ws2|Ws3|Ws4, stride 392.
// ---------------------------------------------------------------------------
__global__ __launch_bounds__(256) void init_w_kernel(
    const float* __restrict__ Wm1, const float* __restrict__ Wm2,
    const float* __restrict__ Wl) {
    int e = blockIdx.x * 256 + threadIdx.x;          // 0..24575
    const float* src; int colbase;
    if (e < 4096)       { src = Wm1; colbase = 0; }
    else if (e < 12288) { src = Wm2; colbase = 64;  e -= 4096; }
    else                { src = Wl;  colbase = 192; e -= 12288; }
    int k = e >> 6, n = e & 63;
    float v = src[k * 64 + n];
    __nv_bfloat16 h = __float2bfloat16(v);
    __nv_bfloat16 l = __float2bfloat16(v - __bfloat162float(h));
    uint32_t off = (uint32_t)(n * 392 + colbase + k) * 2;
    *(__nv_bfloat16*)(g_Wpk + off)         = h;
    *(__nv_bfloat16*)(g_Wpk + 50176 + off) = l;
}

// ---------------------------------------------------------------------------
// One k16-chunk: B via 4x LDSM4 (hi) + 4x LDSM4 (lo), 24 MMA (hh, hl, lh).
// a0..a3 hi and lo are this lane's A fragment; bH/bL = lane ldmatrix base
// already offset to this chunk's k position.
// ---------------------------------------------------------------------------
__device__ __forceinline__ void mma_chunk(
    uint32_t a0h, uint32_t a1h, uint32_t a2h, uint32_t a3h,
    uint32_t a0l, uint32_t a1l, uint32_t a2l, uint32_t a3l,
    uint32_t bH, uint32_t bL, float acc[8][4]) {
    uint32_t bh[4][4], bl[4][4];
#pragma unroll
    for (int pr = 0; pr < 4; pr++) {
        LDSM4(bh[pr][0], bh[pr][1], bh[pr][2], bh[pr][3], bH + pr * (16 * 784));
        LDSM4(bl[pr][0], bl[pr][1], bl[pr][2], bl[pr][3], bL + pr * (16 * 784));
    }
#pragma unroll
    for (int pr = 0; pr < 4; pr++) {
        MMA16816(acc[2 * pr],     a0h, a1h, a2h, a3h, bh[pr][0], bh[pr][1]);
        MMA16816(acc[2 * pr + 1], a0h, a1h, a2h, a3h, bh[pr][2], bh[pr][3]);
    }
#pragma unroll
    for (int pr = 0; pr < 4; pr++) {
        MMA16816(acc[2 * pr],     a0h, a1h, a2h, a3h, bl[pr][0], bl[pr][1]);
        MMA16816(acc[2 * pr + 1], a0h, a1h, a2h, a3h, bl[pr][2], bl[pr][3]);
    }
#pragma unroll
    for (int pr = 0; pr < 4; pr++) {
        MMA16816(acc[2 * pr],     a0l, a1l, a2l, a3l, bh[pr][0], bh[pr][1]);
        MMA16816(acc[2 * pr + 1], a0l, a1l, a2l, a3l, bh[pr][2], bh[pr][3]);
    }
}

// Epilogue: +R (direct from g_L), optional relu, optional pack into next-layer
// A fragments (registers), max over 16 edges, write out block.
__device__ __forceinline__ void epi(
    float acc[8][4], const float* __restrict__ Rbase, bool do_relu,
    uint32_t* fh, uint32_t* fl, bool store,
    float* __restrict__ outp, int lane) {
    int tg = lane >> 2, tc = lane & 3;
#pragma unroll
    for (int nt = 0; nt < 8; nt++) {
        int n0 = nt * 8 + 2 * tc;
        float2 r = __ldg((const float2*)(Rbase + n0));
        float c0 = acc[nt][0] + r.x, c1 = acc[nt][1] + r.y;
        float c2 = acc[nt][2] + r.x, c3 = acc[nt][3] + r.y;
        if (do_relu) {
            c0 = fmaxf(c0, 0.f); c1 = fmaxf(c1, 0.f);
            c2 = fmaxf(c2, 0.f); c3 = fmaxf(c3, 0.f);
        }
        if (store) {
            int s = nt >> 1, o = (nt & 1) * 2;
            hilo2(c0, c1, fh[4 * s + o],     fl[4 * s + o]);
            hilo2(c2, c3, fh[4 * s + o + 1], fl[4 * s + o + 1]);
        }
        float m0 = fmaxf(c0, c2), m1 = fmaxf(c1, c3);
        m0 = fmaxf(m0, __shfl_xor_sync(0xffffffffu, m0, 4));
        m0 = fmaxf(m0, __shfl_xor_sync(0xffffffffu, m0, 8));
        m0 = fmaxf(m0, __shfl_xor_sync(0xffffffffu, m0, 16));
        m1 = fmaxf(m1, __shfl_xor_sync(0xffffffffu, m1, 4));
        m1 = fmaxf(m1, __shfl_xor_sync(0xffffffffu, m1, 8));
        m1 = fmaxf(m1, __shfl_xor_sync(0xffffffffu, m1, 16));
        if (tg == 0) *(float2*)(outp + n0) = make_float2(m0, m1);
    }
}

// ---------------------------------------------------------------------------
// Main edge-MLP: one warp = one point; activations register-resident as MMA
// fragments; smem holds weights only.
// ---------------------------------------------------------------------------
__global__ __launch_bounds__(256, 1) void edge_mlp_kernel(
    const float* __restrict__ x, float* __restrict__ out) {

    extern __shared__ char sm[];
    int t = threadIdx.x, lane = t & 31, w = t >> 5;

    for (int i = t; i < 100352 / 16; i += 256)
        ((uint4*)sm)[i] = __ldg((const uint4*)g_Wpk + i);
    __syncthreads();

    uint32_t smb = smem_to_u32(sm);
    int tg = lane >> 2, tc = lane & 3;
    int n_in_pair = (lane & 7) + ((lane >> 4) & 1) * 8;
    int kh = (lane >> 3) & 1;
    uint32_t bHb = smb + n_in_pair * 784 + kh * 16;
    uint32_t bLb = bHb + WBYTES;

    for (int p = blockIdx.x * 8 + w; p < TOTPTS; p += 148 * 8) {
        int b = p >> 12;

        uint32_t f1h[16], f1l[16], f2h[16], f2l[16], f3h[16], f3l[16];

        // ---- Gather: H1 fragments direct from global + fused H1 max ----
        {
            int j0 = __ldg(g_idx + p * KNN + tg);
            int j1 = __ldg(g_idx + p * KNN + tg + 8);
            const float* P  = g_L + p * 256;
            const float* Q0 = g_Q + ((b << 12) + j0) * 64;
            const float* Q1 = g_Q + ((b << 12) + j1) * 64;
            float hm[16];
#pragma unroll
            for (int s = 0; s < 4; s++) {
                int c = 16 * s + 2 * tc;
                float2 p0 = __ldg((const float2*)(P + c));
                float2 p1 = __ldg((const float2*)(P + c + 8));
                float2 q00 = __ldg((const float2*)(Q0 + c));
                float2 q01 = __ldg((const float2*)(Q0 + c + 8));
                float2 q10 = __ldg((const float2*)(Q1 + c));
                float2 q11 = __ldg((const float2*)(Q1 + c + 8));
                float a0x = fmaxf(p0.x + q00.x, 0.f), a0y = fmaxf(p0.y + q00.y, 0.f);
                float a1x = fmaxf(p0.x + q10.x, 0.f), a1y = fmaxf(p0.y + q10.y, 0.f);
                float a2x = fmaxf(p1.x + q01.x, 0.f), a2y = fmaxf(p1.y + q01.y, 0.f);
                float a3x = fmaxf(p1.x + q11.x, 0.f), a3y = fmaxf(p1.y + q11.y, 0.f);
                hilo2(a0x, a0y, f1h[4 * s + 0], f1l[4 * s + 0]);
                hilo2(a1x, a1y, f1h[4 * s + 1], f1l[4 * s + 1]);
                hilo2(a2x, a2y, f1h[4 * s + 2], f1l[4 * s + 2]);
                hilo2(a3x, a3y, f1h[4 * s + 3], f1l[4 * s + 3]);
                hm[4 * s + 0] = fmaxf(a0x, a1x);
                hm[4 * s + 1] = fmaxf(a0y, a1y);
                hm[4 * s + 2] = fmaxf(a2x, a3x);
                hm[4 * s + 3] = fmaxf(a2y, a3y);
            }
#pragma unroll
            for (int i = 0; i < 16; i++) {
                float mv = hm[i];
                mv = fmaxf(mv, __shfl_xor_sync(0xffffffffu, mv, 4));
                mv = fmaxf(mv, __shfl_xor_sync(0xffffffffu, mv, 8));
                mv = fmaxf(mv, __shfl_xor_sync(0xffffffffu, mv, 16));
                hm[i] = mv;
            }
            if (tg == 0) {
                float* dst = out + p * 320 + 192;
#pragma unroll
                for (int s = 0; s < 4; s++) {
                    int c = 16 * s + 2 * tc;
                    *(float2*)(dst + c)     = make_float2(hm[4 * s + 0], hm[4 * s + 1]);
                    *(float2*)(dst + c + 8) = make_float2(hm[4 * s + 2], hm[4 * s + 3]);
                }
            }
            float2 xv = __ldg((const float2*)(x + p * 64 + lane * 2));
            *(float2*)(out + p * 320 + 256 + lane * 2) = xv;
        }

        float acc[8][4];

        // ---- Layer 2: H2 = relu(H1 @ Ws2 + R1); B k-cols 0..63 ----
#pragma unroll
        for (int i = 0; i < 8; i++)
#pragma unroll
            for (int q2 = 0; q2 < 4; q2++) acc[i][q2] = 0.f;
#pragma unroll
        for (int s = 0; s < 4; s++)
            mma_chunk(f1h[4*s], f1h[4*s+1], f1h[4*s+2], f1h[4*s+3],
                      f1l[4*s], f1l[4*s+1], f1l[4*s+2], f1l[4*s+3],
                      bHb + (0 + 16 * s) * 2, bLb + (0 + 16 * s) * 2, acc);
        epi(acc, g_L + p * 256 + 64, true, f2h, f2l, true,
            out + p * 320 + 128, lane);

        // ---- Layer 3: H3 = relu([H2|H1] @ Ws3 + R2); B k-cols 64..191 ----
#pragma unroll
        for (int i = 0; i < 8; i++)
#pragma unroll
            for (int q2 = 0; q2 < 4; q2++) acc[i][q2] = 0.f;
#pragma unroll
        for (int s = 0; s < 4; s++)
            mma_chunk(f2h[4*s], f2h[4*s+1], f2h[4*s+2], f2h[4*s+3],
                      f2l[4*s], f2l[4*s+1], f2l[4*s+2], f2l[4*s+3],
                      bHb + (64 + 16 * s) * 2, bLb + (64 + 16 * s) * 2, acc);
#pragma unroll
        for (int s = 4; s < 8; s++)
            mma_chunk(f1h[4*(s-4)], f1h[4*(s-4)+1], f1h[4*(s-4)+2], f1h[4*(s-4)+3],
                      f1l[4*(s-4)], f1l[4*(s-4)+1], f1l[4*(s-4)+2], f1l[4*(s-4)+3],
                      bHb + (64 + 16 * s) * 2, bLb + (64 + 16 * s) * 2, acc);
        epi(acc, g_L + p * 256 + 128, true, f3h, f3l, true,
            out + p * 320 + 64, lane);

        // ---- Layer 4: H4 = [H3|H2|H1] @ Ws4 + R3 (no relu); B k-cols 192..383 ----
#pragma unroll
        for (int i = 0; i < 8; i++)
#pragma unroll
            for (int q2 = 0; q2 < 4; q2++) acc[i][q2] = 0.f;
#pragma unroll
        for (int s = 0; s < 4; s++)
            mma_chunk(f3h[4*s], f3h[4*s+1], f3h[4*s+2], f3h[4*s+3],
                      f3l[4*s], f3l[4*s+1], f3l[4*s+2], f3l[4*s+3],
                      bHb + (192 + 16 * s) * 2, bLb + (192 + 16 * s) * 2, acc);
#pragma unroll
        for (int s = 4; s < 8; s++)
            mma_chunk(f2h[4*(s-4)], f2h[4*(s-4)+1], f2h[4*(s-4)+2], f2h[4*(s-4)+3],
                      f2l[4*(s-4)], f2l[4*(s-4)+1], f2l[4*(s-4)+2], f2l[4*(s-4)+3],
                      bHb + (192 + 16 * s) * 2, bLb + (192 + 16 * s) * 2, acc);
#pragma unroll
        for (int s = 8; s < 12; s++)
            mma_chunk(f1h[4*(s-8)], f1h[4*(s-8)+1], f1h[4*(s-8)+2], f1h[4*(s-8)+3],
                      f1l[4*(s-8)], f1l[4*(s-8)+1], f1l[4*(s-8)+2], f1l[4*(s-8)+3],
                      bHb + (192 + 16 * s) * 2, bLb + (192 + 16 * s) * 2, acc);
        epi(acc, g_L + p * 256 + 192, false, f2h, f2l, false,
            out + p * 320, lane);
    }
}

// ---------------------------------------------------------------------------
extern "C" void kernel_launch(void* const* d_in, const int* in_sizes, int n_in,
                              void* d_out, int out_size) {
    const float* x   = (const float*)d_in[0];
    const float* pos = (const float*)d_in[1];
    const float* Wf  = (const float*)d_in[2];
    const float* bf  = (const float*)d_in[3];
    const float* Wm1 = (const float*)d_in[4];
    const float* bm1 = (const float*)d_in[5];
    const float* Wm2 = (const float*)d_in[6];
    const float* bm2 = (const float*)d_in[7];
    const float* Wl  = (const float*)d_in[8];
    const float* bl  = (const float*)d_in[9];
    float* out = (float*)d_out;

    cudaFuncSetAttribute(knn_kernel,
                         cudaFuncAttributeMaxDynamicSharedMemorySize,
                         KNN_SMEM_BYTES);
    cudaFuncSetAttribute(edge_mlp_kernel,
                         cudaFuncAttributeMaxDynamicSharedMemorySize,
                         MAIN_SMEM_BYTES);

    init_w_kernel<<<96, 256>>>(Wm1, Wm2, Wl);
    knn_kernel<<<TOTPTS / QPB, 256, KNN_SMEM_BYTES>>>(pos);
    pre_kernel<<<256, 256>>>(x, Wf, bf, Wm1, bm1, Wm2, bm2, Wl, bl);
    edge_mlp_kernel<<<148, 256, MAIN_SMEM_BYTES>>>(x, out);
}

// round 11
// speedup vs baseline: 3.4217x; 1.0127x over previous
#include <cuda_runtime.h>
#include <cuda_bf16.h>
#include <cstdint>

#define TOTPTS 16384
#define NPTS   4096
#define KNN    16

// ---- knn v6 config: 16 queries/block x 16 subs ----
#define QPB  16
#define SUBS 16
#define TILE 256
#define KNN_SMEM_BYTES (TILE * 16 + QPB * TILE * 4 + QPB * KNN * 4 * 2 + QPB * 8)

// ---- edge_mlp smem: weights only ----
#define WBYTES  50176            // 64*392*2
#define MAIN_SMEM_BYTES 100352   // hi + lo

// Scratch (allocation-free rule: device globals)
__device__ __align__(16) float g_L[TOTPTS * 256];   // [P | R1 | R2 | R3] per point
__device__ __align__(16) float g_Q[TOTPTS * 64];    // Q per point
__device__ int g_idx[TOTPTS * KNN];
__device__ __align__(16) unsigned char g_Wpk[100352]; // packed bf16 hi(50176)+lo(50176)

// ===================== helpers =====================
__device__ __forceinline__ uint32_t smem_to_u32(const void* p) {
    uint32_t a;
    asm("{ .reg .u64 t; cvta.to.shared.u64 t, %1; cvt.u32.u64 %0, t; }" : "=r"(a) : "l"(p));
    return a;
}
#define LDSM4(r0, r1, r2, r3, addr) \
    asm volatile("ldmatrix.sync.aligned.m8n8.x4.shared.b16 {%0,%1,%2,%3}, [%4];" \
        : "=r"(r0), "=r"(r1), "=r"(r2), "=r"(r3) : "r"(addr))
#define MMA16816(c, a0, a1, a2, a3, b0, b1) \
    asm volatile("mma.sync.aligned.m16n8k16.row.col.f32.bf16.bf16.f32 " \
        "{%0,%1,%2,%3}, {%4,%5,%6,%7}, {%8,%9}, {%0,%1,%2,%3};" \
        : "+f"((c)[0]), "+f"((c)[1]), "+f"((c)[2]), "+f"((c)[3]) \
        : "r"(a0), "r"(a1), "r"(a2), "r"(a3), "r"(b0), "r"(b1))

__device__ __forceinline__ void hilo2(float a, float b, uint32_t& h, uint32_t& l) {
    __nv_bfloat16 ha = __float2bfloat16(a), hb = __float2bfloat16(b);
    float ra = a - __bfloat162float(ha), rb = b - __bfloat162float(hb);
    __nv_bfloat162 H; H.x = ha; H.y = hb;
    __nv_bfloat162 L; L.x = __float2bfloat16(ra); L.y = __float2bfloat16(rb);
    h = *(uint32_t*)&H; l = *(uint32_t*)&L;
}

// ---------------------------------------------------------------------------
// KNN v6: phase A = 16 subs x top-1 (union of 16 disjoint sub-minima bounds
// the 16th order statistic => provable tau0); phase B = tau-filter + refine.
// Same distance formula as all passing rounds => identical selection.
// ---------------------------------------------------------------------------
__global__ __launch_bounds__(256) void knn_kernel(const float* __restrict__ pos) {
    extern __shared__ char kshm[];
    float4* sp    = (float4*)kshm;                                     // 4 KB
    int*    bufI  = (int*)(kshm + TILE * 16);                          // 16 KB
    float*  seedD = (float*)(kshm + TILE * 16 + QPB * TILE * 4);       // 1 KB
    int*    seedI = (int*)(kshm + TILE * 16 + QPB * TILE * 4 + QPB * KNN * 4);
    int*    scnt  = (int*)(kshm + TILE * 16 + QPB * TILE * 4 + QPB * KNN * 8);
    float*  stau  = (float*)(kshm + TILE * 16 + QPB * TILE * 4 + QPB * KNN * 8 + QPB * 4);

    int t   = threadIdx.x;
    int ql  = t >> 4;                      // 0..15 query within block
    int sub = t & 15;
    int qg  = blockIdx.x * QPB + ql;
    int b   = qg >> 12;
    int q   = qg & 4095;
    const float* pb = pos + b * NPTS * 3;

    if (t < QPB) scnt[t] = 0;

    float qx = __ldg(pb + q * 3 + 0);
    float qy = __ldg(pb + q * 3 + 1);
    float qz = __ldg(pb + q * 3 + 2);
    float qn = qx * qx + qy * qy + qz * qz;

    float rqx = 0.f, rqy = 0.f, rqz = 0.f, rqn = 0.f;
    if (t < QPB) {
        int rq = (blockIdx.x * QPB + t) & 4095;
        rqx = __ldg(pb + rq * 3 + 0);
        rqy = __ldg(pb + rq * 3 + 1);
        rqz = __ldg(pb + rq * 3 + 2);
        rqn = rqx * rqx + rqy * rqy + rqz * rqz;
    }

    // ---- Phase A: per-(query,sub) top-1 over 256 candidates ----
    float s0 = 3.0e38f;
    int   i0 = 0;

    for (int t0 = 0; t0 < NPTS; t0 += TILE) {
        __syncthreads();
        {
            int j = t0 + t;
            float x = pb[j * 3 + 0], y = pb[j * 3 + 1], z = pb[j * 3 + 2];
            sp[t] = make_float4(x, y, z, x * x + y * y + z * z);
        }
        __syncthreads();
#pragma unroll 8
        for (int jj = 0; jj < TILE / SUBS; jj++) {
            int jl = sub + (jj << 4);
            float4 c = sp[jl];
            float dot = qx * c.x;
            dot = fmaf(qy, c.y, dot);
            dot = fmaf(qz, c.z, dot);
            float d2 = fmaf(dot, -2.0f, qn + c.w);
            int jg = t0 + jl;
            if (d2 < s0 && jg != q) { s0 = d2; i0 = jg; }
        }
    }
    seedD[ql * KNN + sub] = s0;
    seedI[ql * KNN + sub] = i0;
    __syncthreads();

    // ---- Seed refine state: 16 distinct sub-minima; tau0 = their max ----
    float dv[KNN];
    int   iv[KNN];
    float dmax = 0.f;
    int   amax = 0;
    if (t < QPB) {
#pragma unroll
        for (int r = 0; r < KNN; r++) {
            dv[r] = seedD[t * KNN + r];
            iv[r] = seedI[t * KNN + r];
        }
        dmax = dv[0]; amax = 0;
#pragma unroll
        for (int r = 1; r < KNN; r++)
            if (dv[r] > dmax) { dmax = dv[r]; amax = r; }
        stau[t] = dmax;
    }

    // ---- Phase B: tau-filter + per-tile refine (exact, dedup vs seeds) ----
    for (int t0 = 0; t0 < NPTS; t0 += TILE) {
        __syncthreads();
        {
            int j = t0 + t;
            float x = pb[j * 3 + 0], y = pb[j * 3 + 1], z = pb[j * 3 + 2];
            sp[t] = make_float4(x, y, z, x * x + y * y + z * z);
        }
        __syncthreads();

        float tau = stau[ql];
        int*  bI  = bufI + ql * TILE;

#pragma unroll 8
        for (int jj = 0; jj < TILE / SUBS; jj++) {
            int jl = sub + (jj << 4);
            float4 c = sp[jl];
            float dot = qx * c.x;
            dot = fmaf(qy, c.y, dot);
            dot = fmaf(qz, c.z, dot);
            float d2 = fmaf(dot, -2.0f, qn + c.w);
            int jg = t0 + jl;
            if (d2 < tau && jg != q) {
                int slot = atomicAdd(&scnt[ql], 1);
                bI[slot] = jl;
            }
        }
        __syncthreads();

        if (t < QPB) {
            int n = scnt[t];
            const int* rI = bufI + t * TILE;
            for (int e = 0; e < n; e++) {
                int jl = rI[e];
                float4 c = sp[jl];
                float dot = rqx * c.x;
                dot = fmaf(rqy, c.y, dot);
                dot = fmaf(rqz, c.z, dot);
                float d2 = fmaf(dot, -2.0f, rqn + c.w);
                if (d2 < dmax) {
                    int jg = t0 + jl;
                    bool dup = false;
#pragma unroll
                    for (int r = 0; r < KNN; r++) dup = dup || (iv[r] == jg);
                    if (!dup) {
                        dv[amax] = d2; iv[amax] = jg;
                        dmax = dv[0]; amax = 0;
#pragma unroll
                        for (int r = 1; r < KNN; r++)
                            if (dv[r] > dmax) { dmax = dv[r]; amax = r; }
                    }
                }
            }
            scnt[t] = 0;
            stau[t] = dmax;
        }
    }

    if (t < QPB) {
        int obase = (blockIdx.x * QPB + t) * KNN;
#pragma unroll
        for (int r = 0; r < KNN; r++) g_idx[obase + r] = iv[r];
    }
}

// ---------------------------------------------------------------------------
// Per-point precompute (unchanged)
// ---------------------------------------------------------------------------
__global__ __launch_bounds__(256) void pre_kernel(
    const float* __restrict__ x,
    const float* __restrict__ Wf,  const float* __restrict__ bf,
    const float* __restrict__ Wm1, const float* __restrict__ bm1,
    const float* __restrict__ Wm2, const float* __restrict__ bm2,
    const float* __restrict__ Wl,  const float* __restrict__ bl) {

    __shared__ float sw[4096];
    __shared__ float sx[64 * 68];

    int t   = threadIdx.x;
    int pt0 = blockIdx.x * 64;

    for (int i = t; i < 4096; i += 256) {
        int r = i >> 6, c = i & 63;
        sx[c * 68 + r] = __ldg(x + (pt0 + r) * 64 + c);
    }

    int m0 = (t & 15) * 4;
    int n0 = (t >> 4) * 4;

    for (int sect = 0; sect < 5; sect++) {
        __syncthreads();
        for (int i = t; i < 4096; i += 256) {
            float v;
            if      (sect == 0) v = __ldg(Wf + i)        - __ldg(Wf + 8192 + i);
            else if (sect == 1) v = __ldg(Wf + 4096 + i) + __ldg(Wf + 8192 + i);
            else if (sect == 2) v = __ldg(Wm1 + 4096 + i);
            else if (sect == 3) v = __ldg(Wm2 + 8192 + i);
            else                v = __ldg(Wl + 12288 + i);
            sw[i] = v;
        }
        __syncthreads();

        float acc[4][4];
#pragma unroll
        for (int a = 0; a < 4; a++)
#pragma unroll
            for (int bq = 0; bq < 4; bq++) acc[a][bq] = 0.0f;

#pragma unroll 4
        for (int k = 0; k < 64; k++) {
            float4 av = *(const float4*)(sx + k * 68 + m0);
            float4 wv = *(const float4*)(sw + k * 64 + n0);
            float aa[4] = {av.x, av.y, av.z, av.w};
            float ww[4] = {wv.x, wv.y, wv.z, wv.w};
#pragma unroll
            for (int mi = 0; mi < 4; mi++)
#pragma unroll
                for (int ni = 0; ni < 4; ni++)
                    acc[mi][ni] = fmaf(aa[mi], ww[ni], acc[mi][ni]);
        }

        float4 bb = make_float4(0.f, 0.f, 0.f, 0.f);
        const float* bp = (sect == 0) ? bf : (sect == 2) ? bm1
                         : (sect == 3) ? bm2 : (sect == 4) ? bl : nullptr;
        if (bp) bb = __ldg((const float4*)(bp + n0));

#pragma unroll
        for (int mi = 0; mi < 4; mi++) {
            int pt = pt0 + m0 + mi;
            float4 o = make_float4(acc[mi][0] + bb.x, acc[mi][1] + bb.y,
                                   acc[mi][2] + bb.z, acc[mi][3] + bb.w);
            float* dst;
            if (sect == 1) dst = g_Q + pt * 64 + n0;
            else {
                int off = (sect == 0) ? 0 : (sect == 2) ? 64 : (sect == 3) ? 128 : 192;
                dst = g_L + pt * 256 + off + n0;
            }
            *(float4*)dst = o;
        }
    }
}

// ---------------------------------------------------------------------------
// Weight repack: [n=64][k] row-major bf16 hi/lo, k-concat Ws2|Ws3|Ws4, stride 392.
// ---------------------------------------------------------------------------
__global__ __launch_bounds__(256) void init_w_kernel(
    const float* __restrict__ Wm1, const float* __restrict__ Wm2,
    const float* __restrict__ Wl) {
    int e = blockIdx.x * 256 + threadIdx.x;          // 0..24575
    const float* src; int colbase;
    if (e < 4096)       { src = Wm1; colbase = 0; }
    else if (e < 12288) { src = Wm2; colbase = 64;  e -= 4096; }
    else                { src = Wl;  colbase = 192; e -= 12288; }
    int k = e >> 6, n = e & 63;
    float v = src[k * 64 + n];
    __nv_bfloat16 h = __float2bfloat16(v);
    __nv_bfloat16 l = __float2bfloat16(v - __bfloat162float(h));
    uint32_t off = (uint32_t)(n * 392 + colbase + k) * 2;
    *(__nv_bfloat16*)(g_Wpk + off)         = h;
    *(__nv_bfloat16*)(g_Wpk + 50176 + off) = l;
}

// ---------------------------------------------------------------------------
// One k16-chunk: B via 4x LDSM4 (hi) + 4x LDSM4 (lo), 24 MMA (hh, hl, lh).
// ---------------------------------------------------------------------------
__device__ __forceinline__ void mma_chunk(
    uint32_t a0h, uint32_t a1h, uint32_t a2h, uint32_t a3h,
    uint32_t a0l, uint32_t a1l, uint32_t a2l, uint32_t a3l,
    uint32_t bH, uint32_t bL, float acc[8][4]) {
    uint32_t bh[4][4], bl[4][4];
#pragma unroll
    for (int pr = 0; pr < 4; pr++) {
        LDSM4(bh[pr][0], bh[pr][1], bh[pr][2], bh[pr][3], bH + pr * (16 * 784));
        LDSM4(bl[pr][0], bl[pr][1], bl[pr][2], bl[pr][3], bL + pr * (16 * 784));
    }
#pragma unroll
    for (int pr = 0; pr < 4; pr++) {
        MMA16816(acc[2 * pr],     a0h, a1h, a2h, a3h, bh[pr][0], bh[pr][1]);
        MMA16816(acc[2 * pr + 1], a0h, a1h, a2h, a3h, bh[pr][2], bh[pr][3]);
    }
#pragma unroll
    for (int pr = 0; pr < 4; pr++) {
        MMA16816(acc[2 * pr],     a0h, a1h, a2h, a3h, bl[pr][0], bl[pr][1]);
        MMA16816(acc[2 * pr + 1], a0h, a1h, a2h, a3h, bl[pr][2], bl[pr][3]);
    }
#pragma unroll
    for (int pr = 0; pr < 4; pr++) {
        MMA16816(acc[2 * pr],     a0l, a1l, a2l, a3l, bh[pr][0], bh[pr][1]);
        MMA16816(acc[2 * pr + 1], a0l, a1l, a2l, a3l, bh[pr][2], bh[pr][3]);
    }
}

// Epilogue: +R (direct from g_L), optional relu, optional pack into next-layer
// A fragments (registers), max over 16 edges, write out block.
__device__ __forceinline__ void epi(
    float acc[8][4], const float* __restrict__ Rbase, bool do_relu,
    uint32_t* fh, uint32_t* fl, bool store,
    float* __restrict__ outp, int lane) {
    int tg = lane >> 2, tc = lane & 3;
#pragma unroll
    for (int nt = 0; nt < 8; nt++) {
        int n0 = nt * 8 + 2 * tc;
        float2 r = __ldg((const float2*)(Rbase + n0));
        float c0 = acc[nt][0] + r.x, c1 = acc[nt][1] + r.y;
        float c2 = acc[nt][2] + r.x, c3 = acc[nt][3] + r.y;
        if (do_relu) {
            c0 = fmaxf(c0, 0.f); c1 = fmaxf(c1, 0.f);
            c2 = fmaxf(c2, 0.f); c3 = fmaxf(c3, 0.f);
        }
        if (store) {
            int s = nt >> 1, o = (nt & 1) * 2;
            hilo2(c0, c1, fh[4 * s + o],     fl[4 * s + o]);
            hilo2(c2, c3, fh[4 * s + o + 1], fl[4 * s + o + 1]);
        }
        float m0 = fmaxf(c0, c2), m1 = fmaxf(c1, c3);
        m0 = fmaxf(m0, __shfl_xor_sync(0xffffffffu, m0, 4));
        m0 = fmaxf(m0, __shfl_xor_sync(0xffffffffu, m0, 8));
        m0 = fmaxf(m0, __shfl_xor_sync(0xffffffffu, m0, 16));
        m1 = fmaxf(m1, __shfl_xor_sync(0xffffffffu, m1, 4));
        m1 = fmaxf(m1, __shfl_xor_sync(0xffffffffu, m1, 8));
        m1 = fmaxf(m1, __shfl_xor_sync(0xffffffffu, m1, 16));
        if (tg == 0) *(float2*)(outp + n0) = make_float2(m0, m1);
    }
}

// ---------------------------------------------------------------------------
// Main edge-MLP: one warp = one point; activations register-resident as MMA
// fragments; smem holds weights only.
// ---------------------------------------------------------------------------
__global__ __launch_bounds__(256, 1) void edge_mlp_kernel(
    const float* __restrict__ x, float* __restrict__ out) {

    extern __shared__ char sm[];
    int t = threadIdx.x, lane = t & 31, w = t >> 5;

    for (int i = t; i < 100352 / 16; i += 256)
        ((uint4*)sm)[i] = __ldg((const uint4*)g_Wpk + i);
    __syncthreads();

    uint32_t smb = smem_to_u32(sm);
    int tg = lane >> 2, tc = lane & 3;
    int n_in_pair = (lane & 7) + ((lane >> 4) & 1) * 8;
    int kh = (lane >> 3) & 1;
    uint32_t bHb = smb + n_in_pair * 784 + kh * 16;
    uint32_t bLb = bHb + WBYTES;

    for (int p = blockIdx.x * 8 + w; p < TOTPTS; p += 148 * 8) {
        int b = p >> 12;

        uint32_t f1h[16], f1l[16], f2h[16], f2l[16], f3h[16], f3l[16];

        // ---- Gather: H1 fragments direct from global + fused H1 max ----
        {
            int j0 = __ldg(g_idx + p * KNN + tg);
            int j1 = __ldg(g_idx + p * KNN + tg + 8);
            const float* P  = g_L + p * 256;
            const float* Q0 = g_Q + ((b << 12) + j0) * 64;
            const float* Q1 = g_Q + ((b << 12) + j1) * 64;
            float hm[16];
#pragma unroll
            for (int s = 0; s < 4; s++) {
                int c = 16 * s + 2 * tc;
                float2 p0 = __ldg((const float2*)(P + c));
                float2 p1 = __ldg((const float2*)(P + c + 8));
                float2 q00 = __ldg((const float2*)(Q0 + c));
                float2 q01 = __ldg((const float2*)(Q0 + c + 8));
                float2 q10 = __ldg((const float2*)(Q1 + c));
                float2 q11 = __ldg((const float2*)(Q1 + c + 8));
                float a0x = fmaxf(p0.x + q00.x, 0.f), a0y = fmaxf(p0.y + q00.y, 0.f);
                float a1x = fmaxf(p0.x + q10.x, 0.f), a1y = fmaxf(p0.y + q10.y, 0.f);
                float a2x = fmaxf(p1.x + q01.x, 0.f), a2y = fmaxf(p1.y + q01.y, 0.f);
                float a3x = fmaxf(p1.x + q11.x, 0.f), a3y = fmaxf(p1.y + q11.y, 0.f);
                hilo2(a0x, a0y, f1h[4 * s + 0], f1l[4 * s + 0]);
                hilo2(a1x, a1y, f1h[4 * s + 1], f1l[4 * s + 1]);
                hilo2(a2x, a2y, f1h[4 * s + 2], f1l[4 * s + 2]);
                hilo2(a3x, a3y, f1h[4 * s + 3], f1l[4 * s + 3]);
                hm[4 * s + 0] = fmaxf(a0x, a1x);
                hm[4 * s + 1] = fmaxf(a0y, a1y);
                hm[4 * s + 2] = fmaxf(a2x, a3x);
                hm[4 * s + 3] = fmaxf(a2y, a3y);
            }
#pragma unroll
            for (int i = 0; i < 16; i++) {
                float mv = hm[i];
                mv = fmaxf(mv, __shfl_xor_sync(0xffffffffu, mv, 4));
                mv = fmaxf(mv, __shfl_xor_sync(0xffffffffu, mv, 8));
                mv = fmaxf(mv, __shfl_xor_sync(0xffffffffu, mv, 16));
                hm[i] = mv;
            }
            if (tg == 0) {
                float* dst = out + p * 320 + 192;
#pragma unroll
                for (int s = 0; s < 4; s++) {
                    int c = 16 * s + 2 * tc;
                    *(float2*)(dst + c)     = make_float2(hm[4 * s + 0], hm[4 * s + 1]);
                    *(float2*)(dst + c + 8) = make_float2(hm[4 * s + 2], hm[4 * s + 3]);
                }
            }
            float2 xv = __ldg((const float2*)(x + p * 64 + lane * 2));
            *(float2*)(out + p * 320 + 256 + lane * 2) = xv;
        }

        float acc[8][4];

        // ---- Layer 2: H2 = relu(H1 @ Ws2 + R1); B k-cols 0..63 ----
#pragma unroll
        for (int i = 0; i < 8; i++)
#pragma unroll
            for (int q2 = 0; q2 < 4; q2++) acc[i][q2] = 0.f;
#pragma unroll
        for (int s = 0; s < 4; s++)
            mma_chunk(f1h[4*s], f1h[4*s+1], f1h[4*s+2], f1h[4*s+3],
                      f1l[4*s], f1l[4*s+1], f1l[4*s+2], f1l[4*s+3],
                      bHb + (0 + 16 * s) * 2, bLb + (0 + 16 * s) * 2, acc);
        epi(acc, g_L + p * 256 + 64, true, f2h, f2l, true,
            out + p * 320 + 128, lane);

        // ---- Layer 3: H3 = relu([H2|H1] @ Ws3 + R2); B k-cols 64..191 ----
#pragma unroll
        for (int i = 0; i < 8; i++)
#pragma unroll
            for (int q2 = 0; q2 < 4; q2++) acc[i][q2] = 0.f;
#pragma unroll
        for (int s = 0; s < 4; s++)
            mma_chunk(f2h[4*s], f2h[4*s+1], f2h[4*s+2], f2h[4*s+3],
                      f2l[4*s], f2l[4*s+1], f2l[4*s+2], f2l[4*s+3],
                      bHb + (64 + 16 * s) * 2, bLb + (64 + 16 * s) * 2, acc);
#pragma unroll
        for (int s = 4; s < 8; s++)
            mma_chunk(f1h[4*(s-4)], f1h[4*(s-4)+1], f1h[4*(s-4)+2], f1h[4*(s-4)+3],
                      f1l[4*(s-4)], f1l[4*(s-4)+1], f1l[4*(s-4)+2], f1l[4*(s-4)+3],
                      bHb + (64 + 16 * s) * 2, bLb + (64 + 16 * s) * 2, acc);
        epi(acc, g_L + p * 256 + 128, true, f3h, f3l, true,
            out + p * 320 + 64, lane);

        // ---- Layer 4: H4 = [H3|H2|H1] @ Ws4 + R3 (no relu); B k-cols 192..383 ----
#pragma unroll
        for (int i = 0; i < 8; i++)
#pragma unroll
            for (int q2 = 0; q2 < 4; q2++) acc[i][q2] = 0.f;
#pragma unroll
        for (int s = 0; s < 4; s++)
            mma_chunk(f3h[4*s], f3h[4*s+1], f3h[4*s+2], f3h[4*s+3],
                      f3l[4*s], f3l[4*s+1], f3l[4*s+2], f3l[4*s+3],
                      bHb + (192 + 16 * s) * 2, bLb + (192 + 16 * s) * 2, acc);
#pragma unroll
        for (int s = 4; s < 8; s++)
            mma_chunk(f2h[4*(s-4)], f2h[4*(s-4)+1], f2h[4*(s-4)+2], f2h[4*(s-4)+3],
                      f2l[4*(s-4)], f2l[4*(s-4)+1], f2l[4*(s-4)+2], f2l[4*(s-4)+3],
                      bHb + (192 + 16 * s) * 2, bLb + (192 + 16 * s) * 2, acc);
#pragma unroll
        for (int s = 8; s < 12; s++)
            mma_chunk(f1h[4*(s-8)], f1h[4*(s-8)+1], f1h[4*(s-8)+2], f1h[4*(s-8)+3],
                      f1l[4*(s-8)], f1l[4*(s-8)+1], f1l[4*(s-8)+2], f1l[4*(s-8)+3],
                      bHb + (192 + 16 * s) * 2, bLb + (192 + 16 * s) * 2, acc);
        epi(acc, g_L + p * 256 + 192, false, f2h, f2l, false,
            out + p * 320, lane);
    }
}

// ---------------------------------------------------------------------------
extern "C" void kernel_launch(void* const* d_in, const int* in_sizes, int n_in,
                              void* d_out, int out_size) {
    const float* x   = (const float*)d_in[0];
    const float* pos = (const float*)d_in[1];
    const float* Wf  = (const float*)d_in[2];
    const float* bf  = (const float*)d_in[3];
    const float* Wm1 = (const float*)d_in[4];
    const float* bm1 = (const float*)d_in[5];
    const float* Wm2 = (const float*)d_in[6];
    const float* bm2 = (const float*)d_in[7];
    const float* Wl  = (const float*)d_in[8];
    const float* bl  = (const float*)d_in[9];
    float* out = (float*)d_out;

    cudaFuncSetAttribute(knn_kernel,
                         cudaFuncAttributeMaxDynamicSharedMemorySize,
                         KNN_SMEM_BYTES);
    cudaFuncSetAttribute(edge_mlp_kernel,
                         cudaFuncAttributeMaxDynamicSharedMemorySize,
                         MAIN_SMEM_BYTES);

    init_w_kernel<<<96, 256>>>(Wm1, Wm2, Wl);
    knn_kernel<<<TOTPTS / QPB, 256, KNN_SMEM_BYTES>>>(pos);
    pre_kernel<<<256, 256>>>(x, Wf, bf, Wm1, bm1, Wm2, bm2, Wl, bl);
    edge_mlp_kernel<<<148, 256, MAIN_SMEM_BYTES>>>(x, out);
}